// round 13
// baseline (speedup 1.0000x reference)
#include <cuda_runtime.h>
#include <cuda_bf16.h>
#include <cstdint>

#define NFEAT 64
#define NHID  128
#define MAXN  65536

typedef unsigned long long ull;
typedef unsigned short ushort_t;

// ---------------- device scratch (allocation-free contract) ----------------
__device__ __align__(256) float g_agg[MAXN * NFEAT];         // x + neighbor sum
__device__ __align__(256) uint2 g_h1s[MAXN * NHID / 2];      // h1 split: {hipair, lopair}
__device__ __align__(256) float g_stats[256];
__device__ __align__(256) float g_inv_sigma[2];
__device__ __align__(256) ushort_t g_w1hi[NHID * NFEAT];
__device__ __align__(256) ushort_t g_w1lo[NHID * NFEAT];
__device__ int g_idx_mode;

// ---------------- helpers ----------------
__device__ __forceinline__ void bsplit(float v, ushort_t& hi, ushort_t& lo) {
    __nv_bfloat16 h = __float2bfloat16(v);
    float r = v - __bfloat162float(h);
    __nv_bfloat16 l = __float2bfloat16(r);
    hi = __bfloat16_as_ushort(h);
    lo = __bfloat16_as_ushort(l);
}
__device__ __forceinline__ unsigned pk(ushort_t a, ushort_t b) {
    return (unsigned)a | ((unsigned)b << 16);
}
__device__ __forceinline__ void ldsm4(unsigned& r0, unsigned& r1, unsigned& r2, unsigned& r3,
                                      unsigned addr) {
    asm volatile("ldmatrix.sync.aligned.m8n8.x4.shared.b16 {%0,%1,%2,%3}, [%4];"
                 : "=r"(r0), "=r"(r1), "=r"(r2), "=r"(r3) : "r"(addr));
}
__device__ __forceinline__ unsigned smem_u32(const void* p) {
    return (unsigned)__cvta_generic_to_shared(p);
}
__device__ __forceinline__ void cpasync16(unsigned smaddr, const void* g) {
    asm volatile("cp.async.cg.shared.global [%0], [%1], 16;" :: "r"(smaddr), "l"(g));
}
#define CP_COMMIT() asm volatile("cp.async.commit_group;" ::: "memory")
#define CP_WAIT0()  asm volatile("cp.async.wait_group 0;" ::: "memory")

// ---------------- edge dtype probe ----------------
__global__ void detect_kernel(const long long* __restrict__ ei64, int N) {
    int t = threadIdx.x;  // 64 threads
    long long v = ei64[t];
    unsigned bad = __ballot_sync(0xffffffffu, (v < 0 || v >= (long long)N));
    __shared__ unsigned sb[2];
    if ((t & 31) == 0) sb[t >> 5] = bad;
    __syncthreads();
    if (t == 0) g_idx_mode = (sb[0] | sb[1]) ? 1 : 0;
}

// ---------------- setup: stats zero + spectral norms (side stream) ----------------
__device__ float block_reduce_sum256(float v, float* sred) {
    int t = threadIdx.x;
    sred[t] = v;
    __syncthreads();
    for (int s = 128; s > 0; s >>= 1) {
        if (t < s) sred[t] += sred[t + s];
        __syncthreads();
    }
    float r = sred[0];
    __syncthreads();
    return r;
}

__device__ float inv_sigma_calc(const float* __restrict__ W, const float* __restrict__ u,
                                int n, int m, float* sv, float* swv, float* sred) {
    int t = threadIdx.x;
    float vt = 0.f;
    if (t < m) {
#pragma unroll 4
        for (int i = 0; i < n; i++) vt += W[i * m + t] * u[i];
    }
    float s = block_reduce_sum256((t < m) ? vt * vt : 0.f, sred);
    if (t < m) sv[t] = vt / (sqrtf(s) + 1e-12f);
    __syncthreads();
    int warp = t >> 5, lane = t & 31;
    for (int row = warp; row < n; row += 8) {
        float p = 0.f;
        for (int k = lane; k < m; k += 32) p += W[row * m + k] * sv[k];
#pragma unroll
        for (int mask = 16; mask > 0; mask >>= 1)
            p += __shfl_xor_sync(0xffffffffu, p, mask);
        if (lane == 0) swv[row] = p;
    }
    __syncthreads();
    float z = (t < n) ? swv[t] * swv[t] : 0.f;
    float s2 = block_reduce_sum256(z, sred);
    float sig = s2 / (sqrtf(s2) + 1e-12f);
    return 1.f / sig;
}

__global__ void setup_kernel(float* __restrict__ stats,
                             const float* __restrict__ W1, const float* __restrict__ u1,
                             const float* __restrict__ W2, const float* __restrict__ u2,
                             float* __restrict__ inv_sigma) {
    __shared__ float sv[128];
    __shared__ float swv[128];
    __shared__ float sred[256];
    int t = threadIdx.x;
    stats[t] = 0.f;

    float is1 = inv_sigma_calc(W1, u1, NHID, NFEAT, sv, swv, sred);
    float is2 = inv_sigma_calc(W2, u2, NHID, NHID, sv, swv, sred);
    if (t == 0) { inv_sigma[0] = is1; inv_sigma[1] = is2; }
}

// ---------------- parallel W1 split ----------------
__global__ void wsplit1_kernel(const float* __restrict__ W1,
                               const float* __restrict__ inv_sigma,
                               ushort_t* __restrict__ w1hi, ushort_t* __restrict__ w1lo) {
    int i = blockIdx.x * blockDim.x + threadIdx.x;
    if (i >= NHID * NFEAT) return;
    float w = W1[i] * inv_sigma[0];
    ushort_t hi, lo;
    bsplit(w, hi, lo);
    w1hi[i] = hi;
    w1lo[i] = lo;
}

// ---------------- scatter: agg[dst] += x[src], 8 thr/edge ----------------
__global__ void scatter_kernel(const void* __restrict__ eiv,
                               const float4* __restrict__ x4,
                               float4* __restrict__ h4, int E, int N) {
    int i = blockIdx.x * blockDim.x + threadIdx.x;
    if (i >= E * 8) return;
    int e = i >> 3;
    int c = i & 7;
    long long s, d;
    if (g_idx_mode == 0) {
        const long long* ei = (const long long*)eiv;
        s = ei[e];
        d = ei[E + e];
    } else {
        const int* ei = (const int*)eiv;
        s = ei[e];
        d = ei[E + e];
    }
    if ((ull)s >= (ull)N || (ull)d >= (ull)N) return;
    const float4* xs = x4 + s * 16 + c;
    float4 v0 = __ldcg(xs);
    float4 v1 = __ldcg(xs + 8);
    float4* p = h4 + d * 16 + c;
    asm volatile("red.global.add.v4.f32 [%0], {%1,%2,%3,%4};"
                 :: "l"(p), "f"(v0.x), "f"(v0.y), "f"(v0.z), "f"(v0.w) : "memory");
    asm volatile("red.global.add.v4.f32 [%0], {%1,%2,%3,%4};"
                 :: "l"(p + 8), "f"(v1.x), "f"(v1.y), "f"(v1.z), "f"(v1.w) : "memory");
}

// ---------------- tensor-core GEMM, hi/lo segments, ldmatrix ----------------
// MODE 1 (gemm1): A = agg (= x + neighbor sum), split on fly; relu; fused stats;
//                 h1 interleaved out; B = pre-split W1 via cp.async.
// MODE 2 (gemm2): A = interleaved pre-split h1; B = BN+SN fold of fp32 W2 done
//                 in-prologue (af/cf from stats); b2eff computed per block; fp32 out.
template <int K, int NC, int MODE>
__global__ void __launch_bounds__(512, 2) gemm_kernel(
    const float* __restrict__ inF, const uint2* __restrict__ inS,
    const ushort_t* __restrict__ whi, const ushort_t* __restrict__ wlo,
    const float* __restrict__ W2, const float* __restrict__ gamma,
    const float* __restrict__ beta, const float* __restrict__ b2,
    const float* __restrict__ inv_sigma, int Nrows,
    const float* __restrict__ bias,
    float* __restrict__ outF, uint2* __restrict__ outS,
    float* __restrict__ gstats) {
    constexpr bool G1 = (MODE == 1);
    constexpr int SAe = K + 8;
    constexpr int K4 = K / 4;
    constexpr int R8 = K / 8;
    constexpr int CW = NC / 32;
    constexpr int MT = 128 / ((16 / CW) * 16);
    constexpr int CB = 128 / NC;
    constexpr bool SPLITX = (MT == 1);

    extern __shared__ ushort_t smu[];
    ushort_t* sAhi = smu;                        // 128*SAe
    ushort_t* sAlo = sAhi + 128 * SAe;
    ushort_t* sBhi = sAlo + 128 * SAe;           // NC*SAe
    ushort_t* sBlo = sBhi + NC * SAe;
    float* sBias   = reinterpret_cast<float*>(sBlo + NC * SAe);   // NC floats
    float* sStats  = sBias + NC;                                  // 256 floats

    const int tid = threadIdx.x;
    const int cb = blockIdx.x % CB;
    const int row0 = (blockIdx.x / CB) * 128;
    const int fcol0 = cb * NC;

    if (G1) {
        // ---- B fill via cp.async (pre-split W1) ----
        const uint4* ghi = reinterpret_cast<const uint4*>(whi + (size_t)fcol0 * K);
        const uint4* glo = reinterpret_cast<const uint4*>(wlo + (size_t)fcol0 * K);
#pragma unroll
        for (int q = tid; q < NC * R8; q += 512) {
            int f = q / R8, c = q - f * R8;
            cpasync16(smem_u32(&sBhi[f * SAe + c * 8]), ghi + q);
            cpasync16(smem_u32(&sBlo[f * SAe + c * 8]), glo + q);
        }
        CP_COMMIT();
        if (tid < NC) sBias[tid] = bias[fcol0 + tid];
        if (tid < 256) sStats[tid] = 0.f;

        // ---- A fill: agg (already x + neighbors) -> bf16 hi/lo ----
        const float4* in4 = reinterpret_cast<const float4*>(inF);
#pragma unroll
        for (int q = tid; q < 128 * K4; q += 512) {
            int r = q / K4, c = q - r * K4;
            float4 v = __ldcg(in4 + (size_t)(row0 + r) * K4 + c);
            ushort_t h0, l0, h1, l1, h2, l2, h3, l3;
            bsplit(v.x, h0, l0); bsplit(v.y, h1, l1);
            bsplit(v.z, h2, l2); bsplit(v.w, h3, l3);
            uint2 hw, lw;
            hw.x = pk(h0, h1); hw.y = pk(h2, h3);
            lw.x = pk(l0, l1); lw.y = pk(l2, l3);
            *reinterpret_cast<uint2*>(&sAhi[r * SAe + c * 4]) = hw;
            *reinterpret_cast<uint2*>(&sAlo[r * SAe + c * 4]) = lw;
        }
        CP_WAIT0();
        __syncthreads();
    } else {
        // ---- af/cf from stats ----
        if (tid < 128) {
            float invN = 1.f / (float)Nrows;
            float mean = gstats[tid] * invN;
            float var = gstats[128 + tid] * invN - mean * mean;
            float af = gamma[tid] * rsqrtf(var + 1e-5f);
            sStats[tid] = af;                       // af
            sStats[128 + tid] = beta[tid] - mean * af;  // cf
        }
        __syncthreads();

        // ---- B fold: fp32 W2 slice -> bf16 hi/lo + b2eff slice ----
        {
            const float is2 = inv_sigma[1];
            const int t = tid >> 3;            // 0..63 (output row within slice)
            const int fo = (tid & 7) * 16;     // f chunk start
            const float* w2row = W2 + (size_t)(fcol0 + t) * 128 + fo;
            float bacc = 0.f;
#pragma unroll
            for (int j = 0; j < 16; j += 2) {
                float wsn0 = w2row[j] * is2;
                float wsn1 = w2row[j + 1] * is2;
                float we0 = wsn0 * sStats[fo + j];
                float we1 = wsn1 * sStats[fo + j + 1];
                ushort_t h0, l0, h1, l1;
                bsplit(we0, h0, l0); bsplit(we1, h1, l1);
                *reinterpret_cast<unsigned*>(&sBhi[t * SAe + fo + j]) = pk(h0, h1);
                *reinterpret_cast<unsigned*>(&sBlo[t * SAe + fo + j]) = pk(l0, l1);
                bacc += sStats[128 + fo + j] * wsn0 + sStats[128 + fo + j + 1] * wsn1;
            }
#pragma unroll
            for (int m = 4; m > 0; m >>= 1)
                bacc += __shfl_xor_sync(0xffffffffu, bacc, m);
            if ((tid & 7) == 0) sBias[t] = b2[fcol0 + t] + bacc;
        }

        // ---- A fill: interleaved pre-split h1 ----
        const uint4* gs = reinterpret_cast<const uint4*>(inS);
        constexpr int RW = K / 4;
#pragma unroll
        for (int q = tid; q < 128 * RW; q += 512) {
            int r = q / RW, c = q - r * RW;
            uint4 v = __ldcg(gs + (size_t)(row0 + r) * RW + c);
            *reinterpret_cast<uint2*>(&sAhi[r * SAe + c * 4]) = make_uint2(v.x, v.z);
            *reinterpret_cast<uint2*>(&sAlo[r * SAe + c * 4]) = make_uint2(v.y, v.w);
        }
        __syncthreads();
    }

    const int wid = tid >> 5;
    const int lane = tid & 31;
    const int g = lane >> 2;
    const int tg = lane & 3;
    const int rowBase = (wid / CW) * (MT * 16);
    const int colBase = (wid % CW) * 32;

    float acc[MT][4][4];
    float accX[SPLITX ? MT : 1][4][4];
#pragma unroll
    for (int m = 0; m < MT; m++)
#pragma unroll
        for (int n = 0; n < 4; n++)
#pragma unroll
            for (int i = 0; i < 4; i++) {
                acc[m][n][i] = 0.f;
                if (SPLITX) accX[m][n][i] = 0.f;
            }

    const unsigned aRow = rowBase + (lane & 15);
    const unsigned aKH = (lane >> 4) * 8;
    const unsigned aHiBase = smem_u32(sAhi) + (aRow * SAe + aKH) * 2;
    const unsigned aLoBase = smem_u32(sAlo) + (aRow * SAe + aKH) * 2;
    const unsigned bRow = colBase + (lane & 7) + ((lane >> 4) << 3);
    const unsigned bKH = ((lane >> 3) & 1) * 8;
    const unsigned bHiBase = smem_u32(sBhi) + (bRow * SAe + bKH) * 2;
    const unsigned bLoBase = smem_u32(sBlo) + (bRow * SAe + bKH) * 2;
    constexpr unsigned MSTEP = 16 * SAe * 2;

#define MMA(ACC, A0, A1, A2, A3, B0, B1)                                       \
    asm volatile(                                                              \
        "mma.sync.aligned.m16n8k16.row.col.f32.bf16.bf16.f32 "                 \
        "{%0,%1,%2,%3}, {%4,%5,%6,%7}, {%8,%9}, {%0,%1,%2,%3};"                \
        : "+f"((ACC)[0]), "+f"((ACC)[1]), "+f"((ACC)[2]), "+f"((ACC)[3])       \
        : "r"(A0), "r"(A1), "r"(A2), "r"(A3), "r"(B0), "r"(B1))

#pragma unroll
    for (int kk = 0; kk < K / 16; kk++) {
        const unsigned ko2 = kk * 32;
        unsigned ahi[MT][4], bhi[2][4], blo[2][4], alo[MT][4];
#pragma unroll
        for (int m = 0; m < MT; m++)
            ldsm4(ahi[m][0], ahi[m][1], ahi[m][2], ahi[m][3], aHiBase + ko2 + m * MSTEP);
#pragma unroll
        for (int p = 0; p < 2; p++)
            ldsm4(bhi[p][0], bhi[p][1], bhi[p][2], bhi[p][3], bHiBase + ko2 + p * MSTEP);
#pragma unroll
        for (int m = 0; m < MT; m++)
#pragma unroll
            for (int n = 0; n < 4; n++)
                MMA(acc[m][n], ahi[m][0], ahi[m][1], ahi[m][2], ahi[m][3],
                    bhi[n >> 1][(n & 1) * 2], bhi[n >> 1][(n & 1) * 2 + 1]);
#pragma unroll
        for (int p = 0; p < 2; p++)
            ldsm4(blo[p][0], blo[p][1], blo[p][2], blo[p][3], bLoBase + ko2 + p * MSTEP);
#pragma unroll
        for (int m = 0; m < MT; m++)
#pragma unroll
            for (int n = 0; n < 4; n++) {
                if (SPLITX)
                    MMA(accX[m][n], ahi[m][0], ahi[m][1], ahi[m][2], ahi[m][3],
                        blo[n >> 1][(n & 1) * 2], blo[n >> 1][(n & 1) * 2 + 1]);
                else
                    MMA(acc[m][n], ahi[m][0], ahi[m][1], ahi[m][2], ahi[m][3],
                        blo[n >> 1][(n & 1) * 2], blo[n >> 1][(n & 1) * 2 + 1]);
            }
#pragma unroll
        for (int m = 0; m < MT; m++)
            ldsm4(alo[m][0], alo[m][1], alo[m][2], alo[m][3], aLoBase + ko2 + m * MSTEP);
#pragma unroll
        for (int m = 0; m < MT; m++)
#pragma unroll
            for (int n = 0; n < 4; n++) {
                if (SPLITX)
                    MMA(accX[m][n], alo[m][0], alo[m][1], alo[m][2], alo[m][3],
                        bhi[n >> 1][(n & 1) * 2], bhi[n >> 1][(n & 1) * 2 + 1]);
                else
                    MMA(acc[m][n], alo[m][0], alo[m][1], alo[m][2], alo[m][3],
                        bhi[n >> 1][(n & 1) * 2], bhi[n >> 1][(n & 1) * 2 + 1]);
            }
    }
#undef MMA

    if (SPLITX) {
#pragma unroll
        for (int m = 0; m < MT; m++)
#pragma unroll
            for (int n = 0; n < 4; n++)
#pragma unroll
                for (int i = 0; i < 4; i++) acc[m][n][i] += accX[m][n][i];
    }

    // ---- epilogue ----
    float cs[4][2], css[4][2];
    if (G1) {
#pragma unroll
        for (int n = 0; n < 4; n++) { cs[n][0] = cs[n][1] = css[n][0] = css[n][1] = 0.f; }
    }
#pragma unroll
    for (int m = 0; m < MT; m++) {
        int r = row0 + rowBase + m * 16 + g;
#pragma unroll
        for (int n = 0; n < 4; n++) {
            int f = colBase + n * 8 + tg * 2;
            float bx = sBias[f], by = sBias[f + 1];
            float2 o0 = make_float2(acc[m][n][0] + bx, acc[m][n][1] + by);
            float2 o1 = make_float2(acc[m][n][2] + bx, acc[m][n][3] + by);
            if (G1) {
                o0.x = fmaxf(o0.x, 0.f); o0.y = fmaxf(o0.y, 0.f);
                o1.x = fmaxf(o1.x, 0.f); o1.y = fmaxf(o1.y, 0.f);
                cs[n][0] += o0.x + o1.x;  cs[n][1] += o0.y + o1.y;
                css[n][0] += o0.x * o0.x + o1.x * o1.x;
                css[n][1] += o0.y * o0.y + o1.y * o1.y;
                ushort_t ha, la, hb, lb;
                size_t i0 = ((size_t)r * 128 + fcol0 + f) >> 1;
                size_t i1 = ((size_t)(r + 8) * 128 + fcol0 + f) >> 1;
                bsplit(o0.x, ha, la); bsplit(o0.y, hb, lb);
                outS[i0] = make_uint2(pk(ha, hb), pk(la, lb));
                bsplit(o1.x, ha, la); bsplit(o1.y, hb, lb);
                outS[i1] = make_uint2(pk(ha, hb), pk(la, lb));
            } else {
                *reinterpret_cast<float2*>(&outF[(size_t)r * 128 + fcol0 + f]) = o0;
                *reinterpret_cast<float2*>(&outF[(size_t)(r + 8) * 128 + fcol0 + f]) = o1;
            }
        }
    }
    if (G1) {
#pragma unroll
        for (int mask = 4; mask < 32; mask <<= 1) {
#pragma unroll
            for (int n = 0; n < 4; n++) {
#pragma unroll
                for (int j = 0; j < 2; j++) {
                    cs[n][j] += __shfl_xor_sync(0xffffffffu, cs[n][j], mask);
                    css[n][j] += __shfl_xor_sync(0xffffffffu, css[n][j], mask);
                }
            }
        }
        __syncthreads();  // sStats reused as accumulation buffer after prologue zeroing
        if (lane < 4) {
#pragma unroll
            for (int n = 0; n < 4; n++) {
#pragma unroll
                for (int j = 0; j < 2; j++) {
                    int f = colBase + n * 8 + lane * 2 + j;
                    atomicAdd(&sStats[f], cs[n][j]);
                    atomicAdd(&sStats[128 + f], css[n][j]);
                }
            }
        }
        __syncthreads();
        if (tid < 256) atomicAdd(&gstats[tid], sStats[tid]);
    }
}

// ---------------- launch ----------------
extern "C" void kernel_launch(void* const* d_in, const int* in_sizes, int n_in,
                              void* d_out, int out_size) {
    const float* x        = (const float*)d_in[0];
    const void*  ei       = d_in[1];
    const float* W1       = (const float*)d_in[2];
    const float* b1       = (const float*)d_in[3];
    const float* u1       = (const float*)d_in[4];
    const float* gamma    = (const float*)d_in[5];
    const float* beta     = (const float*)d_in[6];
    const float* W2       = (const float*)d_in[7];
    const float* b2       = (const float*)d_in[8];
    const float* u2       = (const float*)d_in[9];

    int N = in_sizes[0] / NFEAT;
    int E = in_sizes[1] / 2;

    float *pAgg, *pStats, *pInv;
    uint2 *pH1s;
    ushort_t *pW1hi, *pW1lo;
    cudaGetSymbolAddress((void**)&pAgg, g_agg);
    cudaGetSymbolAddress((void**)&pH1s, g_h1s);
    cudaGetSymbolAddress((void**)&pStats, g_stats);
    cudaGetSymbolAddress((void**)&pInv, g_inv_sigma);
    cudaGetSymbolAddress((void**)&pW1hi, g_w1hi);
    cudaGetSymbolAddress((void**)&pW1lo, g_w1lo);

    // one-time side stream + fork/join events
    static cudaStream_t s_side = nullptr;
    static cudaEvent_t s_fork = nullptr, s_join = nullptr, s_init = nullptr;
    if (!s_side) {
        cudaStreamCreateWithFlags(&s_side, cudaStreamNonBlocking);
        cudaEventCreateWithFlags(&s_fork, cudaEventDisableTiming);
        cudaEventCreateWithFlags(&s_join, cudaEventDisableTiming);
        cudaEventCreateWithFlags(&s_init, cudaEventDisableTiming);
    }

    // fork: side stream does agg=x copy + spectral norms + W1 split
    cudaEventRecord(s_fork, 0);
    cudaStreamWaitEvent(s_side, s_fork, 0);
    cudaMemcpyAsync(pAgg, x, (size_t)N * NFEAT * sizeof(float),
                    cudaMemcpyDeviceToDevice, s_side);
    cudaEventRecord(s_init, s_side);
    setup_kernel<<<1, 256, 0, s_side>>>(pStats, W1, u1, W2, u2, pInv);
    wsplit1_kernel<<<(NHID * NFEAT + 255) / 256, 256, 0, s_side>>>(W1, pInv, pW1hi, pW1lo);
    cudaEventRecord(s_join, s_side);

    // main stream: detect (overlaps copy) -> wait copy -> scatter
    detect_kernel<<<1, 64>>>((const long long*)ei, N);
    cudaStreamWaitEvent(0, s_init, 0);
    int items = E * 8;
    scatter_kernel<<<(items + 255) / 256, 256>>>(ei, (const float4*)x, (float4*)pAgg, E, N);

    // join before gemm1
    cudaStreamWaitEvent(0, s_join, 0);

    // gemm1: h1(interleaved split) = relu(agg @ W1s^T + b1), fused stats
    {
        constexpr int SAe = NFEAT + 8;
        int smem = (2 * 128 + 2 * 128) * SAe * 2 + (128 + 256) * 4;
        cudaFuncSetAttribute((const void*)gemm_kernel<NFEAT, 128, 1>,
                             cudaFuncAttributeMaxDynamicSharedMemorySize, smem);
        gemm_kernel<NFEAT, 128, 1><<<N / 128, 512, smem>>>(
            pAgg, nullptr, pW1hi, pW1lo,
            nullptr, nullptr, nullptr, nullptr, nullptr, N,
            b1, nullptr, pH1s, pStats);
    }

    // gemm2: out = h1 @ W2eff^T + b2eff  (BN+SN fold fused into prologue)
    {
        constexpr int SAe = NHID + 8;
        int smem = (2 * 128 + 2 * 64) * SAe * 2 + (64 + 256) * 4;
        cudaFuncSetAttribute((const void*)gemm_kernel<NHID, 64, 2>,
                             cudaFuncAttributeMaxDynamicSharedMemorySize, smem);
        gemm_kernel<NHID, 64, 2><<<(N / 128) * 2, 512, smem>>>(
            nullptr, pH1s, nullptr, nullptr,
            W2, gamma, beta, b2, pInv, N,
            nullptr, (float*)d_out, nullptr, pStats);
    }
}

// round 14
// speedup vs baseline: 1.1583x; 1.1583x over previous
#include <cuda_runtime.h>
#include <cuda_bf16.h>
#include <cstdint>

#define NFEAT 64
#define NHID  128
#define MAXN  65536

typedef unsigned long long ull;
typedef unsigned short ushort_t;

// ---------------- device scratch (allocation-free contract) ----------------
__device__ __align__(256) float g_agg[MAXN * NFEAT];         // x + neighbor sum
__device__ __align__(256) uint2 g_h1s[MAXN * NHID / 2];      // h1 split: {hipair, lopair}
__device__ __align__(256) float g_stats[256];
__device__ __align__(256) float g_inv_sigma[2];
__device__ __align__(256) float g_b2eff[NHID];
__device__ __align__(256) ushort_t g_w1hi[NHID * NFEAT];
__device__ __align__(256) ushort_t g_w1lo[NHID * NFEAT];
__device__ __align__(256) ushort_t g_w2hi[NHID * NHID];
__device__ __align__(256) ushort_t g_w2lo[NHID * NHID];
__device__ int g_idx_mode;

// ---------------- helpers ----------------
__device__ __forceinline__ void bsplit(float v, ushort_t& hi, ushort_t& lo) {
    __nv_bfloat16 h = __float2bfloat16(v);
    float r = v - __bfloat162float(h);
    __nv_bfloat16 l = __float2bfloat16(r);
    hi = __bfloat16_as_ushort(h);
    lo = __bfloat16_as_ushort(l);
}
__device__ __forceinline__ unsigned pk(ushort_t a, ushort_t b) {
    return (unsigned)a | ((unsigned)b << 16);
}
__device__ __forceinline__ void ldsm4(unsigned& r0, unsigned& r1, unsigned& r2, unsigned& r3,
                                      unsigned addr) {
    asm volatile("ldmatrix.sync.aligned.m8n8.x4.shared.b16 {%0,%1,%2,%3}, [%4];"
                 : "=r"(r0), "=r"(r1), "=r"(r2), "=r"(r3) : "r"(addr));
}
__device__ __forceinline__ unsigned smem_u32(const void* p) {
    return (unsigned)__cvta_generic_to_shared(p);
}
__device__ __forceinline__ void cpasync16(unsigned smaddr, const void* g) {
    asm volatile("cp.async.cg.shared.global [%0], [%1], 16;" :: "r"(smaddr), "l"(g));
}
#define CP_COMMIT() asm volatile("cp.async.commit_group;" ::: "memory")
#define CP_WAIT0()  asm volatile("cp.async.wait_group 0;" ::: "memory")

// ---------------- edge dtype probe ----------------
__global__ void detect_kernel(const long long* __restrict__ ei64, int N) {
    int t = threadIdx.x;  // 64 threads
    long long v = ei64[t];
    unsigned bad = __ballot_sync(0xffffffffu, (v < 0 || v >= (long long)N));
    __shared__ unsigned sb[2];
    if ((t & 31) == 0) sb[t >> 5] = bad;
    __syncthreads();
    if (t == 0) g_idx_mode = (sb[0] | sb[1]) ? 1 : 0;
}

// ---------------- setup: stats zero + spectral norms (side stream) ----------------
__device__ float block_reduce_sum256(float v, float* sred) {
    int t = threadIdx.x;
    sred[t] = v;
    __syncthreads();
    for (int s = 128; s > 0; s >>= 1) {
        if (t < s) sred[t] += sred[t + s];
        __syncthreads();
    }
    float r = sred[0];
    __syncthreads();
    return r;
}

__device__ float inv_sigma_calc(const float* __restrict__ W, const float* __restrict__ u,
                                int n, int m, float* sv, float* swv, float* sred) {
    int t = threadIdx.x;
    float vt = 0.f;
    if (t < m) {
#pragma unroll 4
        for (int i = 0; i < n; i++) vt += W[i * m + t] * u[i];
    }
    float s = block_reduce_sum256((t < m) ? vt * vt : 0.f, sred);
    if (t < m) sv[t] = vt / (sqrtf(s) + 1e-12f);
    __syncthreads();
    int warp = t >> 5, lane = t & 31;
    for (int row = warp; row < n; row += 8) {
        float p = 0.f;
        for (int k = lane; k < m; k += 32) p += W[row * m + k] * sv[k];
#pragma unroll
        for (int mask = 16; mask > 0; mask >>= 1)
            p += __shfl_xor_sync(0xffffffffu, p, mask);
        if (lane == 0) swv[row] = p;
    }
    __syncthreads();
    float z = (t < n) ? swv[t] * swv[t] : 0.f;
    float s2 = block_reduce_sum256(z, sred);
    float sig = s2 / (sqrtf(s2) + 1e-12f);
    return 1.f / sig;
}

__global__ void setup_kernel(float* __restrict__ stats,
                             const float* __restrict__ W1, const float* __restrict__ u1,
                             const float* __restrict__ W2, const float* __restrict__ u2,
                             float* __restrict__ inv_sigma) {
    __shared__ float sv[128];
    __shared__ float swv[128];
    __shared__ float sred[256];
    int t = threadIdx.x;
    stats[t] = 0.f;

    float is1 = inv_sigma_calc(W1, u1, NHID, NFEAT, sv, swv, sred);
    float is2 = inv_sigma_calc(W2, u2, NHID, NHID, sv, swv, sred);
    if (t == 0) { inv_sigma[0] = is1; inv_sigma[1] = is2; }
}

// ---------------- parallel W1 split ----------------
__global__ void wsplit1_kernel(const float* __restrict__ W1,
                               const float* __restrict__ inv_sigma,
                               ushort_t* __restrict__ w1hi, ushort_t* __restrict__ w1lo) {
    int i = blockIdx.x * blockDim.x + threadIdx.x;
    if (i >= NHID * NFEAT) return;
    float w = W1[i] * inv_sigma[0];
    ushort_t hi, lo;
    bsplit(w, hi, lo);
    w1hi[i] = hi;
    w1lo[i] = lo;
}

// ---------------- scatter: agg[dst] += x[src], 8 thr/edge ----------------
__global__ void scatter_kernel(const void* __restrict__ eiv,
                               const float4* __restrict__ x4,
                               float4* __restrict__ h4, int E, int N) {
    int i = blockIdx.x * blockDim.x + threadIdx.x;
    if (i >= E * 8) return;
    int e = i >> 3;
    int c = i & 7;
    long long s, d;
    if (g_idx_mode == 0) {
        const long long* ei = (const long long*)eiv;
        s = ei[e];
        d = ei[E + e];
    } else {
        const int* ei = (const int*)eiv;
        s = ei[e];
        d = ei[E + e];
    }
    if ((ull)s >= (ull)N || (ull)d >= (ull)N) return;
    const float4* xs = x4 + s * 16 + c;
    float4 v0 = __ldcg(xs);
    float4 v1 = __ldcg(xs + 8);
    float4* p = h4 + d * 16 + c;
    asm volatile("red.global.add.v4.f32 [%0], {%1,%2,%3,%4};"
                 :: "l"(p), "f"(v0.x), "f"(v0.y), "f"(v0.z), "f"(v0.w) : "memory");
    asm volatile("red.global.add.v4.f32 [%0], {%1,%2,%3,%4};"
                 :: "l"(p + 8), "f"(v1.x), "f"(v1.y), "f"(v1.z), "f"(v1.w) : "memory");
}

// ---------------- tensor-core GEMM, hi/lo segments, ldmatrix + cp.async ----------------
// MODE 1 (gemm1): A = agg (= x + neighbor sum), split on the fly; relu; fused stats;
//                 h1 interleaved out.
// MODE 2 (gemm2): A = interleaved pre-split h1 (deinterleave fill), fp32 out.
template <int K, int NC, int MODE>
__global__ void __launch_bounds__(512, 2) gemm_kernel(
    const float* __restrict__ inF,
    const uint2* __restrict__ inS,
    const ushort_t* __restrict__ whi, const ushort_t* __restrict__ wlo,
    const float* __restrict__ bias,
    float* __restrict__ outF, uint2* __restrict__ outS,
    float* __restrict__ gstats) {
    constexpr bool G1 = (MODE == 1);
    constexpr int SAe = K + 8;
    constexpr int K4 = K / 4;
    constexpr int R8 = K / 8;
    constexpr int CW = NC / 32;
    constexpr int MT = 128 / ((16 / CW) * 16);
    constexpr int CB = 128 / NC;
    constexpr bool SPLITX = (MT == 1);

    extern __shared__ ushort_t smu[];
    ushort_t* sAhi = smu;                        // 128*SAe
    ushort_t* sAlo = sAhi + 128 * SAe;
    ushort_t* sBhi = sAlo + 128 * SAe;           // NC*SAe
    ushort_t* sBlo = sBhi + NC * SAe;
    float* sBias   = reinterpret_cast<float*>(sBlo + NC * SAe);
    float* sStats  = sBias + NC;

    const int tid = threadIdx.x;
    const int cb = blockIdx.x % CB;
    const int row0 = (blockIdx.x / CB) * 128;
    const int fcol0 = cb * NC;

    // ---- B fill via cp.async ----
    {
        const uint4* ghi = reinterpret_cast<const uint4*>(whi + (size_t)fcol0 * K);
        const uint4* glo = reinterpret_cast<const uint4*>(wlo + (size_t)fcol0 * K);
#pragma unroll
        for (int q = tid; q < NC * R8; q += 512) {
            int f = q / R8, c = q - f * R8;
            cpasync16(smem_u32(&sBhi[f * SAe + c * 8]), ghi + q);
            cpasync16(smem_u32(&sBlo[f * SAe + c * 8]), glo + q);
        }
        CP_COMMIT();
    }
    if (tid < NC) sBias[tid] = bias[fcol0 + tid];
    if (G1 && tid < 256) sStats[tid] = 0.f;

    // ---- A fill (L2-only loads: streamed once) ----
    if (G1) {
        const float4* in4 = reinterpret_cast<const float4*>(inF);
#pragma unroll
        for (int q = tid; q < 128 * K4; q += 512) {
            int r = q / K4, c = q - r * K4;
            float4 v = __ldcg(in4 + (size_t)(row0 + r) * K4 + c);
            ushort_t h0, l0, h1, l1, h2, l2, h3, l3;
            bsplit(v.x, h0, l0); bsplit(v.y, h1, l1);
            bsplit(v.z, h2, l2); bsplit(v.w, h3, l3);
            uint2 hw, lw;
            hw.x = pk(h0, h1); hw.y = pk(h2, h3);
            lw.x = pk(l0, l1); lw.y = pk(l2, l3);
            *reinterpret_cast<uint2*>(&sAhi[r * SAe + c * 4]) = hw;
            *reinterpret_cast<uint2*>(&sAlo[r * SAe + c * 4]) = lw;
        }
    } else {
        const uint4* gs = reinterpret_cast<const uint4*>(inS);
        constexpr int RW = K / 4;
#pragma unroll
        for (int q = tid; q < 128 * RW; q += 512) {
            int r = q / RW, c = q - r * RW;
            uint4 v = __ldcg(gs + (size_t)(row0 + r) * RW + c);
            *reinterpret_cast<uint2*>(&sAhi[r * SAe + c * 4]) = make_uint2(v.x, v.z);
            *reinterpret_cast<uint2*>(&sAlo[r * SAe + c * 4]) = make_uint2(v.y, v.w);
        }
    }
    CP_WAIT0();
    __syncthreads();

    const int wid = tid >> 5;
    const int lane = tid & 31;
    const int g = lane >> 2;
    const int tg = lane & 3;
    const int rowBase = (wid / CW) * (MT * 16);
    const int colBase = (wid % CW) * 32;

    float acc[MT][4][4];
    float accX[SPLITX ? MT : 1][4][4];
#pragma unroll
    for (int m = 0; m < MT; m++)
#pragma unroll
        for (int n = 0; n < 4; n++)
#pragma unroll
            for (int i = 0; i < 4; i++) {
                acc[m][n][i] = 0.f;
                if (SPLITX) accX[m][n][i] = 0.f;
            }

    const unsigned aRow = rowBase + (lane & 15);
    const unsigned aKH = (lane >> 4) * 8;
    const unsigned aHiBase = smem_u32(sAhi) + (aRow * SAe + aKH) * 2;
    const unsigned aLoBase = smem_u32(sAlo) + (aRow * SAe + aKH) * 2;
    const unsigned bRow = colBase + (lane & 7) + ((lane >> 4) << 3);
    const unsigned bKH = ((lane >> 3) & 1) * 8;
    const unsigned bHiBase = smem_u32(sBhi) + (bRow * SAe + bKH) * 2;
    const unsigned bLoBase = smem_u32(sBlo) + (bRow * SAe + bKH) * 2;
    constexpr unsigned MSTEP = 16 * SAe * 2;

#define MMA(ACC, A0, A1, A2, A3, B0, B1)                                       \
    asm volatile(                                                              \
        "mma.sync.aligned.m16n8k16.row.col.f32.bf16.bf16.f32 "                 \
        "{%0,%1,%2,%3}, {%4,%5,%6,%7}, {%8,%9}, {%0,%1,%2,%3};"                \
        : "+f"((ACC)[0]), "+f"((ACC)[1]), "+f"((ACC)[2]), "+f"((ACC)[3])       \
        : "r"(A0), "r"(A1), "r"(A2), "r"(A3), "r"(B0), "r"(B1))

#pragma unroll
    for (int kk = 0; kk < K / 16; kk++) {
        const unsigned ko2 = kk * 32;
        unsigned ahi[MT][4], bhi[2][4], blo[2][4], alo[MT][4];
#pragma unroll
        for (int m = 0; m < MT; m++)
            ldsm4(ahi[m][0], ahi[m][1], ahi[m][2], ahi[m][3], aHiBase + ko2 + m * MSTEP);
#pragma unroll
        for (int p = 0; p < 2; p++)
            ldsm4(bhi[p][0], bhi[p][1], bhi[p][2], bhi[p][3], bHiBase + ko2 + p * MSTEP);
#pragma unroll
        for (int m = 0; m < MT; m++)
#pragma unroll
            for (int n = 0; n < 4; n++)
                MMA(acc[m][n], ahi[m][0], ahi[m][1], ahi[m][2], ahi[m][3],
                    bhi[n >> 1][(n & 1) * 2], bhi[n >> 1][(n & 1) * 2 + 1]);
#pragma unroll
        for (int p = 0; p < 2; p++)
            ldsm4(blo[p][0], blo[p][1], blo[p][2], blo[p][3], bLoBase + ko2 + p * MSTEP);
#pragma unroll
        for (int m = 0; m < MT; m++)
#pragma unroll
            for (int n = 0; n < 4; n++) {
                if (SPLITX)
                    MMA(accX[m][n], ahi[m][0], ahi[m][1], ahi[m][2], ahi[m][3],
                        blo[n >> 1][(n & 1) * 2], blo[n >> 1][(n & 1) * 2 + 1]);
                else
                    MMA(acc[m][n], ahi[m][0], ahi[m][1], ahi[m][2], ahi[m][3],
                        blo[n >> 1][(n & 1) * 2], blo[n >> 1][(n & 1) * 2 + 1]);
            }
#pragma unroll
        for (int m = 0; m < MT; m++)
            ldsm4(alo[m][0], alo[m][1], alo[m][2], alo[m][3], aLoBase + ko2 + m * MSTEP);
#pragma unroll
        for (int m = 0; m < MT; m++)
#pragma unroll
            for (int n = 0; n < 4; n++) {
                if (SPLITX)
                    MMA(accX[m][n], alo[m][0], alo[m][1], alo[m][2], alo[m][3],
                        bhi[n >> 1][(n & 1) * 2], bhi[n >> 1][(n & 1) * 2 + 1]);
                else
                    MMA(acc[m][n], alo[m][0], alo[m][1], alo[m][2], alo[m][3],
                        bhi[n >> 1][(n & 1) * 2], bhi[n >> 1][(n & 1) * 2 + 1]);
            }
    }
#undef MMA

    if (SPLITX) {
#pragma unroll
        for (int m = 0; m < MT; m++)
#pragma unroll
            for (int n = 0; n < 4; n++)
#pragma unroll
                for (int i = 0; i < 4; i++) acc[m][n][i] += accX[m][n][i];
    }

    // ---- epilogue ----
    float cs[4][2], css[4][2];
    if (G1) {
#pragma unroll
        for (int n = 0; n < 4; n++) { cs[n][0] = cs[n][1] = css[n][0] = css[n][1] = 0.f; }
    }
#pragma unroll
    for (int m = 0; m < MT; m++) {
        int r = row0 + rowBase + m * 16 + g;
#pragma unroll
        for (int n = 0; n < 4; n++) {
            int f = colBase + n * 8 + tg * 2;
            float bx = sBias[f], by = sBias[f + 1];
            float2 o0 = make_float2(acc[m][n][0] + bx, acc[m][n][1] + by);
            float2 o1 = make_float2(acc[m][n][2] + bx, acc[m][n][3] + by);
            if (G1) {
                o0.x = fmaxf(o0.x, 0.f); o0.y = fmaxf(o0.y, 0.f);
                o1.x = fmaxf(o1.x, 0.f); o1.y = fmaxf(o1.y, 0.f);
                cs[n][0] += o0.x + o1.x;  cs[n][1] += o0.y + o1.y;
                css[n][0] += o0.x * o0.x + o1.x * o1.x;
                css[n][1] += o0.y * o0.y + o1.y * o1.y;
                ushort_t ha, la, hb, lb;
                size_t i0 = ((size_t)r * 128 + fcol0 + f) >> 1;
                size_t i1 = ((size_t)(r + 8) * 128 + fcol0 + f) >> 1;
                bsplit(o0.x, ha, la); bsplit(o0.y, hb, lb);
                outS[i0] = make_uint2(pk(ha, hb), pk(la, lb));
                bsplit(o1.x, ha, la); bsplit(o1.y, hb, lb);
                outS[i1] = make_uint2(pk(ha, hb), pk(la, lb));
            } else {
                *reinterpret_cast<float2*>(&outF[(size_t)r * 128 + fcol0 + f]) = o0;
                *reinterpret_cast<float2*>(&outF[(size_t)(r + 8) * 128 + fcol0 + f]) = o1;
            }
        }
    }
    if (G1) {
#pragma unroll
        for (int mask = 4; mask < 32; mask <<= 1) {
#pragma unroll
            for (int n = 0; n < 4; n++) {
#pragma unroll
                for (int j = 0; j < 2; j++) {
                    cs[n][j] += __shfl_xor_sync(0xffffffffu, cs[n][j], mask);
                    css[n][j] += __shfl_xor_sync(0xffffffffu, css[n][j], mask);
                }
            }
        }
        if (lane < 4) {
#pragma unroll
            for (int n = 0; n < 4; n++) {
#pragma unroll
                for (int j = 0; j < 2; j++) {
                    int f = colBase + n * 8 + lane * 2 + j;
                    atomicAdd(&sStats[f], cs[n][j]);
                    atomicAdd(&sStats[128 + f], css[n][j]);
                }
            }
        }
        __syncthreads();
        if (tid < 256) atomicAdd(&gstats[tid], sStats[tid]);
    }
}

// ---------------- parallel fold BN + SN into split W2eff / b2eff ----------------
__global__ void __launch_bounds__(128) finalize_kernel(
    const float* __restrict__ W2, const float* __restrict__ b2,
    const float* __restrict__ gamma, const float* __restrict__ beta,
    const float* __restrict__ stats, const float* __restrict__ inv_sigma,
    ushort_t* __restrict__ w2hi, ushort_t* __restrict__ w2lo,
    float* __restrict__ b2eff, int N) {
    const int t = blockIdx.x;
    const int f = threadIdx.x;
    float invN = 1.f / (float)N;
    float mean = stats[f] * invN;
    float var = stats[128 + f] * invN - mean * mean;
    float af = gamma[f] * rsqrtf(var + 1e-5f);
    float cf = beta[f] - mean * af;

    float wsn = W2[t * 128 + f] * inv_sigma[1];
    float weff = wsn * af;
    ushort_t hi, lo;
    bsplit(weff, hi, lo);
    w2hi[t * 128 + f] = hi;
    w2lo[t * 128 + f] = lo;

    float v = cf * wsn;
#pragma unroll
    for (int mask = 16; mask > 0; mask >>= 1)
        v += __shfl_xor_sync(0xffffffffu, v, mask);
    __shared__ float sw[4];
    if ((f & 31) == 0) sw[f >> 5] = v;
    __syncthreads();
    if (f == 0) b2eff[t] = b2[t] + sw[0] + sw[1] + sw[2] + sw[3];
}

// ---------------- launch ----------------
extern "C" void kernel_launch(void* const* d_in, const int* in_sizes, int n_in,
                              void* d_out, int out_size) {
    const float* x        = (const float*)d_in[0];
    const void*  ei       = d_in[1];
    const float* W1       = (const float*)d_in[2];
    const float* b1       = (const float*)d_in[3];
    const float* u1       = (const float*)d_in[4];
    const float* gamma    = (const float*)d_in[5];
    const float* beta     = (const float*)d_in[6];
    const float* W2       = (const float*)d_in[7];
    const float* b2       = (const float*)d_in[8];
    const float* u2       = (const float*)d_in[9];

    int N = in_sizes[0] / NFEAT;
    int E = in_sizes[1] / 2;

    float *pAgg, *pStats, *pInv, *pB2eff;
    uint2 *pH1s;
    ushort_t *pW1hi, *pW1lo, *pW2hi, *pW2lo;
    cudaGetSymbolAddress((void**)&pAgg, g_agg);
    cudaGetSymbolAddress((void**)&pH1s, g_h1s);
    cudaGetSymbolAddress((void**)&pStats, g_stats);
    cudaGetSymbolAddress((void**)&pInv, g_inv_sigma);
    cudaGetSymbolAddress((void**)&pB2eff, g_b2eff);
    cudaGetSymbolAddress((void**)&pW1hi, g_w1hi);
    cudaGetSymbolAddress((void**)&pW1lo, g_w1lo);
    cudaGetSymbolAddress((void**)&pW2hi, g_w2hi);
    cudaGetSymbolAddress((void**)&pW2lo, g_w2lo);

    // one-time side stream + fork/join events
    static cudaStream_t s_side = nullptr;
    static cudaEvent_t s_fork = nullptr, s_join = nullptr, s_init = nullptr;
    if (!s_side) {
        cudaStreamCreateWithFlags(&s_side, cudaStreamNonBlocking);
        cudaEventCreateWithFlags(&s_fork, cudaEventDisableTiming);
        cudaEventCreateWithFlags(&s_join, cudaEventDisableTiming);
        cudaEventCreateWithFlags(&s_init, cudaEventDisableTiming);
    }

    // fork: side stream does agg=x copy + spectral norms + W1 split
    cudaEventRecord(s_fork, 0);
    cudaStreamWaitEvent(s_side, s_fork, 0);
    cudaMemcpyAsync(pAgg, x, (size_t)N * NFEAT * sizeof(float),
                    cudaMemcpyDeviceToDevice, s_side);
    cudaEventRecord(s_init, s_side);
    setup_kernel<<<1, 256, 0, s_side>>>(pStats, W1, u1, W2, u2, pInv);
    wsplit1_kernel<<<(NHID * NFEAT + 255) / 256, 256, 0, s_side>>>(W1, pInv, pW1hi, pW1lo);
    cudaEventRecord(s_join, s_side);

    // main stream: detect (overlaps copy) -> wait copy -> scatter
    detect_kernel<<<1, 64>>>((const long long*)ei, N);
    cudaStreamWaitEvent(0, s_init, 0);
    int items = E * 8;
    scatter_kernel<<<(items + 255) / 256, 256>>>(ei, (const float4*)x, (float4*)pAgg, E, N);

    // join before gemm1
    cudaStreamWaitEvent(0, s_join, 0);

    // gemm1: h1(interleaved split) = relu(agg @ W1s^T + b1), fused stats
    {
        constexpr int SAe = NFEAT + 8;
        int smem = (2 * 128 + 2 * 128) * SAe * 2 + (128 + 256) * 4;
        cudaFuncSetAttribute((const void*)gemm_kernel<NFEAT, 128, 1>,
                             cudaFuncAttributeMaxDynamicSharedMemorySize, smem);
        gemm_kernel<NFEAT, 128, 1><<<N / 128, 512, smem>>>(
            pAgg, nullptr, pW1hi, pW1lo, b1,
            nullptr, pH1s, pStats);
    }

    // finalize BN+SN fold (parallel, 128x128)
    finalize_kernel<<<128, 128>>>(W2, b2, gamma, beta, pStats, pInv, pW2hi, pW2lo, pB2eff, N);

    // gemm2: out = h1 @ W2eff^T + b2eff  (split-N 128x64 tiles, split accumulators)
    {
        constexpr int SAe = NHID + 8;
        int smem = (2 * 128 + 2 * 64) * SAe * 2 + (64 + 256) * 4;
        cudaFuncSetAttribute((const void*)gemm_kernel<NHID, 64, 2>,
                             cudaFuncAttributeMaxDynamicSharedMemorySize, smem);
        gemm_kernel<NHID, 64, 2><<<(N / 128) * 2, 512, smem>>>(
            nullptr, pH1s, pW2hi, pW2lo, pB2eff,
            (float*)d_out, nullptr, nullptr);
    }
}

// round 15
// speedup vs baseline: 1.1676x; 1.0081x over previous
#include <cuda_runtime.h>
#include <cuda_bf16.h>
#include <cstdint>

#define NFEAT 64
#define NHID  128
#define MAXN  65536

typedef unsigned long long ull;
typedef unsigned short ushort_t;

// ---------------- device scratch (allocation-free contract) ----------------
__device__ __align__(256) float g_agg[MAXN * NFEAT];         // neighbor sum (zeroed)
__device__ __align__(256) uint2 g_h1s[MAXN * NHID / 2];      // h1 split: {hipair, lopair}
__device__ __align__(256) float g_stats[256];
__device__ __align__(256) float g_inv_sigma[2];
__device__ __align__(256) float g_b2eff[NHID];
__device__ __align__(256) ushort_t g_w1hi[NHID * NFEAT];
__device__ __align__(256) ushort_t g_w1lo[NHID * NFEAT];
__device__ __align__(256) ushort_t g_w2hi[NHID * NHID];
__device__ __align__(256) ushort_t g_w2lo[NHID * NHID];
__device__ int g_idx_mode;

// ---------------- helpers ----------------
__device__ __forceinline__ void bsplit(float v, ushort_t& hi, ushort_t& lo) {
    __nv_bfloat16 h = __float2bfloat16(v);
    float r = v - __bfloat162float(h);
    __nv_bfloat16 l = __float2bfloat16(r);
    hi = __bfloat16_as_ushort(h);
    lo = __bfloat16_as_ushort(l);
}
__device__ __forceinline__ unsigned pk(ushort_t a, ushort_t b) {
    return (unsigned)a | ((unsigned)b << 16);
}
__device__ __forceinline__ void ldsm4(unsigned& r0, unsigned& r1, unsigned& r2, unsigned& r3,
                                      unsigned addr) {
    asm volatile("ldmatrix.sync.aligned.m8n8.x4.shared.b16 {%0,%1,%2,%3}, [%4];"
                 : "=r"(r0), "=r"(r1), "=r"(r2), "=r"(r3) : "r"(addr));
}
__device__ __forceinline__ unsigned smem_u32(const void* p) {
    return (unsigned)__cvta_generic_to_shared(p);
}
__device__ __forceinline__ void cpasync16(unsigned smaddr, const void* g) {
    asm volatile("cp.async.cg.shared.global [%0], [%1], 16;" :: "r"(smaddr), "l"(g));
}
#define CP_COMMIT() asm volatile("cp.async.commit_group;" ::: "memory")
#define CP_WAIT0()  asm volatile("cp.async.wait_group 0;" ::: "memory")

// ---------------- edge dtype probe (side stream) ----------------
__global__ void detect_kernel(const long long* __restrict__ ei64, int N) {
    int t = threadIdx.x;  // 64 threads
    long long v = ei64[t];
    unsigned bad = __ballot_sync(0xffffffffu, (v < 0 || v >= (long long)N));
    __shared__ unsigned sb[2];
    if ((t & 31) == 0) sb[t >> 5] = bad;
    __syncthreads();
    if (t == 0) g_idx_mode = (sb[0] | sb[1]) ? 1 : 0;
}

// ---------------- setup: stats zero + spectral norms (side stream) ----------------
__device__ float block_reduce_sum256(float v, float* sred) {
    int t = threadIdx.x;
    sred[t] = v;
    __syncthreads();
    for (int s = 128; s > 0; s >>= 1) {
        if (t < s) sred[t] += sred[t + s];
        __syncthreads();
    }
    float r = sred[0];
    __syncthreads();
    return r;
}

__device__ float inv_sigma_calc(const float* __restrict__ W, const float* __restrict__ u,
                                int n, int m, float* sv, float* swv, float* sred) {
    int t = threadIdx.x;
    float vt = 0.f;
    if (t < m) {
#pragma unroll 4
        for (int i = 0; i < n; i++) vt += W[i * m + t] * u[i];
    }
    float s = block_reduce_sum256((t < m) ? vt * vt : 0.f, sred);
    if (t < m) sv[t] = vt / (sqrtf(s) + 1e-12f);
    __syncthreads();
    int warp = t >> 5, lane = t & 31;
    for (int row = warp; row < n; row += 8) {
        float p = 0.f;
        for (int k = lane; k < m; k += 32) p += W[row * m + k] * sv[k];
#pragma unroll
        for (int mask = 16; mask > 0; mask >>= 1)
            p += __shfl_xor_sync(0xffffffffu, p, mask);
        if (lane == 0) swv[row] = p;
    }
    __syncthreads();
    float z = (t < n) ? swv[t] * swv[t] : 0.f;
    float s2 = block_reduce_sum256(z, sred);
    float sig = s2 / (sqrtf(s2) + 1e-12f);
    return 1.f / sig;
}

__global__ void setup_kernel(float* __restrict__ stats,
                             const float* __restrict__ W1, const float* __restrict__ u1,
                             const float* __restrict__ W2, const float* __restrict__ u2,
                             float* __restrict__ inv_sigma) {
    __shared__ float sv[128];
    __shared__ float swv[128];
    __shared__ float sred[256];
    int t = threadIdx.x;
    stats[t] = 0.f;

    float is1 = inv_sigma_calc(W1, u1, NHID, NFEAT, sv, swv, sred);
    float is2 = inv_sigma_calc(W2, u2, NHID, NHID, sv, swv, sred);
    if (t == 0) { inv_sigma[0] = is1; inv_sigma[1] = is2; }
}

// ---------------- parallel W1 split ----------------
__global__ void wsplit1_kernel(const float* __restrict__ W1,
                               const float* __restrict__ inv_sigma,
                               ushort_t* __restrict__ w1hi, ushort_t* __restrict__ w1lo) {
    int i = blockIdx.x * blockDim.x + threadIdx.x;
    if (i >= NHID * NFEAT) return;
    float w = W1[i] * inv_sigma[0];
    ushort_t hi, lo;
    bsplit(w, hi, lo);
    w1hi[i] = hi;
    w1lo[i] = lo;
}

// ---------------- scatter: agg[dst] += x[src], 8 thr/edge ----------------
__global__ void scatter_kernel(const void* __restrict__ eiv,
                               const float4* __restrict__ x4,
                               float4* __restrict__ h4, int E, int N) {
    int i = blockIdx.x * blockDim.x + threadIdx.x;
    if (i >= E * 8) return;
    int e = i >> 3;
    int c = i & 7;
    long long s, d;
    if (g_idx_mode == 0) {
        const long long* ei = (const long long*)eiv;
        s = ei[e];
        d = ei[E + e];
    } else {
        const int* ei = (const int*)eiv;
        s = ei[e];
        d = ei[E + e];
    }
    if ((ull)s >= (ull)N || (ull)d >= (ull)N) return;
    const float4* xs = x4 + s * 16 + c;
    float4 v0 = __ldcg(xs);
    float4 v1 = __ldcg(xs + 8);
    float4* p = h4 + d * 16 + c;
    asm volatile("red.global.add.v4.f32 [%0], {%1,%2,%3,%4};"
                 :: "l"(p), "f"(v0.x), "f"(v0.y), "f"(v0.z), "f"(v0.w) : "memory");
    asm volatile("red.global.add.v4.f32 [%0], {%1,%2,%3,%4};"
                 :: "l"(p + 8), "f"(v1.x), "f"(v1.y), "f"(v1.z), "f"(v1.w) : "memory");
}

// ---------------- tensor-core GEMM, hi/lo segments, ldmatrix + cp.async ----------------
// MODE 1 (gemm1): A = agg+x (fp32, split on the fly), relu, fused stats, h1 interleaved out.
// MODE 2 (gemm2): A = interleaved pre-split h1 (deinterleave fill), fp32 out.
// NT row-tiles per block: B tile loaded once, A refilled per tile.
template <int K, int NC, int MODE, int NT>
__global__ void __launch_bounds__(512, 2) gemm_kernel(
    const float* __restrict__ inF, const float* __restrict__ xadd,
    const uint2* __restrict__ inS,
    const ushort_t* __restrict__ whi, const ushort_t* __restrict__ wlo,
    const float* __restrict__ bias,
    float* __restrict__ outF, uint2* __restrict__ outS,
    float* __restrict__ gstats) {
    constexpr bool G1 = (MODE == 1);
    constexpr int SAe = K + 8;
    constexpr int K4 = K / 4;
    constexpr int R8 = K / 8;
    constexpr int CW = NC / 32;
    constexpr int MT = 128 / ((16 / CW) * 16);
    constexpr int CB = 128 / NC;
    constexpr bool SPLITX = (MT == 1);

    extern __shared__ ushort_t smu[];
    ushort_t* sAhi = smu;                        // 128*SAe
    ushort_t* sAlo = sAhi + 128 * SAe;
    ushort_t* sBhi = sAlo + 128 * SAe;           // NC*SAe
    ushort_t* sBlo = sBhi + NC * SAe;
    float* sBias   = reinterpret_cast<float*>(sBlo + NC * SAe);
    float* sStats  = sBias + NC;

    const int tid = threadIdx.x;
    const int cb = blockIdx.x % CB;
    const int tile0 = (blockIdx.x / CB) * NT;
    const int fcol0 = cb * NC;

    // ---- B fill via cp.async (once per block) ----
    {
        const uint4* ghi = reinterpret_cast<const uint4*>(whi + (size_t)fcol0 * K);
        const uint4* glo = reinterpret_cast<const uint4*>(wlo + (size_t)fcol0 * K);
#pragma unroll
        for (int q = tid; q < NC * R8; q += 512) {
            int f = q / R8, c = q - f * R8;
            cpasync16(smem_u32(&sBhi[f * SAe + c * 8]), ghi + q);
            cpasync16(smem_u32(&sBlo[f * SAe + c * 8]), glo + q);
        }
        CP_COMMIT();
    }
    if (tid < NC) sBias[tid] = bias[fcol0 + tid];
    if (G1 && tid < 256) sStats[tid] = 0.f;

    const int wid = tid >> 5;
    const int lane = tid & 31;
    const int g = lane >> 2;
    const int tg = lane & 3;
    const int rowBase = (wid / CW) * (MT * 16);
    const int colBase = (wid % CW) * 32;

    const unsigned aRow = rowBase + (lane & 15);
    const unsigned aKH = (lane >> 4) * 8;
    const unsigned aHiBase = smem_u32(sAhi) + (aRow * SAe + aKH) * 2;
    const unsigned aLoBase = smem_u32(sAlo) + (aRow * SAe + aKH) * 2;
    const unsigned bRow = colBase + (lane & 7) + ((lane >> 4) << 3);
    const unsigned bKH = ((lane >> 3) & 1) * 8;
    const unsigned bHiBase = smem_u32(sBhi) + (bRow * SAe + bKH) * 2;
    const unsigned bLoBase = smem_u32(sBlo) + (bRow * SAe + bKH) * 2;
    constexpr unsigned MSTEP = 16 * SAe * 2;

#define MMA(ACC, A0, A1, A2, A3, B0, B1)                                       \
    asm volatile(                                                              \
        "mma.sync.aligned.m16n8k16.row.col.f32.bf16.bf16.f32 "                 \
        "{%0,%1,%2,%3}, {%4,%5,%6,%7}, {%8,%9}, {%0,%1,%2,%3};"                \
        : "+f"((ACC)[0]), "+f"((ACC)[1]), "+f"((ACC)[2]), "+f"((ACC)[3])       \
        : "r"(A0), "r"(A1), "r"(A2), "r"(A3), "r"(B0), "r"(B1))

#pragma unroll 1
    for (int t = 0; t < NT; t++) {
        const int row0 = (tile0 + t) * 128;
        if (t) __syncthreads();   // all warps done reading previous A tile

        // ---- A fill (L2-only loads) ----
        if (G1) {
            const float4* in4 = reinterpret_cast<const float4*>(inF);
            const float4* x4 = reinterpret_cast<const float4*>(xadd);
#pragma unroll
            for (int q = tid; q < 128 * K4; q += 512) {
                int r = q / K4, c = q - r * K4;
                size_t gi = (size_t)(row0 + r) * K4 + c;
                float4 v = __ldcg(in4 + gi);
                float4 w = __ldcg(x4 + gi);
                v.x += w.x; v.y += w.y; v.z += w.z; v.w += w.w;
                ushort_t h0, l0, h1, l1, h2, l2, h3, l3;
                bsplit(v.x, h0, l0); bsplit(v.y, h1, l1);
                bsplit(v.z, h2, l2); bsplit(v.w, h3, l3);
                uint2 hw, lw;
                hw.x = pk(h0, h1); hw.y = pk(h2, h3);
                lw.x = pk(l0, l1); lw.y = pk(l2, l3);
                *reinterpret_cast<uint2*>(&sAhi[r * SAe + c * 4]) = hw;
                *reinterpret_cast<uint2*>(&sAlo[r * SAe + c * 4]) = lw;
            }
        } else {
            const uint4* gs = reinterpret_cast<const uint4*>(inS);
            constexpr int RW = K / 4;
#pragma unroll
            for (int q = tid; q < 128 * RW; q += 512) {
                int r = q / RW, c = q - r * RW;
                uint4 v = __ldcg(gs + (size_t)(row0 + r) * RW + c);
                *reinterpret_cast<uint2*>(&sAhi[r * SAe + c * 4]) = make_uint2(v.x, v.z);
                *reinterpret_cast<uint2*>(&sAlo[r * SAe + c * 4]) = make_uint2(v.y, v.w);
            }
        }
        if (t == 0) CP_WAIT0();
        __syncthreads();

        float acc[MT][4][4];
        float accX[SPLITX ? MT : 1][4][4];
#pragma unroll
        for (int m = 0; m < MT; m++)
#pragma unroll
            for (int n = 0; n < 4; n++)
#pragma unroll
                for (int i = 0; i < 4; i++) {
                    acc[m][n][i] = 0.f;
                    if (SPLITX) accX[m][n][i] = 0.f;
                }

#pragma unroll
        for (int kk = 0; kk < K / 16; kk++) {
            const unsigned ko2 = kk * 32;
            unsigned ahi[MT][4], bhi[2][4], blo[2][4], alo[MT][4];
#pragma unroll
            for (int m = 0; m < MT; m++)
                ldsm4(ahi[m][0], ahi[m][1], ahi[m][2], ahi[m][3], aHiBase + ko2 + m * MSTEP);
#pragma unroll
            for (int p = 0; p < 2; p++)
                ldsm4(bhi[p][0], bhi[p][1], bhi[p][2], bhi[p][3], bHiBase + ko2 + p * MSTEP);
#pragma unroll
            for (int m = 0; m < MT; m++)
#pragma unroll
                for (int n = 0; n < 4; n++)
                    MMA(acc[m][n], ahi[m][0], ahi[m][1], ahi[m][2], ahi[m][3],
                        bhi[n >> 1][(n & 1) * 2], bhi[n >> 1][(n & 1) * 2 + 1]);
#pragma unroll
            for (int p = 0; p < 2; p++)
                ldsm4(blo[p][0], blo[p][1], blo[p][2], blo[p][3], bLoBase + ko2 + p * MSTEP);
#pragma unroll
            for (int m = 0; m < MT; m++)
#pragma unroll
                for (int n = 0; n < 4; n++) {
                    if (SPLITX)
                        MMA(accX[m][n], ahi[m][0], ahi[m][1], ahi[m][2], ahi[m][3],
                            blo[n >> 1][(n & 1) * 2], blo[n >> 1][(n & 1) * 2 + 1]);
                    else
                        MMA(acc[m][n], ahi[m][0], ahi[m][1], ahi[m][2], ahi[m][3],
                            blo[n >> 1][(n & 1) * 2], blo[n >> 1][(n & 1) * 2 + 1]);
                }
#pragma unroll
            for (int m = 0; m < MT; m++)
                ldsm4(alo[m][0], alo[m][1], alo[m][2], alo[m][3], aLoBase + ko2 + m * MSTEP);
#pragma unroll
            for (int m = 0; m < MT; m++)
#pragma unroll
                for (int n = 0; n < 4; n++) {
                    if (SPLITX)
                        MMA(accX[m][n], alo[m][0], alo[m][1], alo[m][2], alo[m][3],
                            bhi[n >> 1][(n & 1) * 2], bhi[n >> 1][(n & 1) * 2 + 1]);
                    else
                        MMA(acc[m][n], alo[m][0], alo[m][1], alo[m][2], alo[m][3],
                            bhi[n >> 1][(n & 1) * 2], bhi[n >> 1][(n & 1) * 2 + 1]);
                }
        }

        if (SPLITX) {
#pragma unroll
            for (int m = 0; m < MT; m++)
#pragma unroll
                for (int n = 0; n < 4; n++)
#pragma unroll
                    for (int i = 0; i < 4; i++) acc[m][n][i] += accX[m][n][i];
        }

        // ---- epilogue (per tile) ----
        float cs[4][2], css[4][2];
        if (G1) {
#pragma unroll
            for (int n = 0; n < 4; n++) { cs[n][0] = cs[n][1] = css[n][0] = css[n][1] = 0.f; }
        }
#pragma unroll
        for (int m = 0; m < MT; m++) {
            int r = row0 + rowBase + m * 16 + g;
#pragma unroll
            for (int n = 0; n < 4; n++) {
                int f = colBase + n * 8 + tg * 2;
                float bx = sBias[f], by = sBias[f + 1];
                float2 o0 = make_float2(acc[m][n][0] + bx, acc[m][n][1] + by);
                float2 o1 = make_float2(acc[m][n][2] + bx, acc[m][n][3] + by);
                if (G1) {
                    o0.x = fmaxf(o0.x, 0.f); o0.y = fmaxf(o0.y, 0.f);
                    o1.x = fmaxf(o1.x, 0.f); o1.y = fmaxf(o1.y, 0.f);
                    cs[n][0] += o0.x + o1.x;  cs[n][1] += o0.y + o1.y;
                    css[n][0] += o0.x * o0.x + o1.x * o1.x;
                    css[n][1] += o0.y * o0.y + o1.y * o1.y;
                    ushort_t ha, la, hb, lb;
                    size_t i0 = ((size_t)r * 128 + fcol0 + f) >> 1;
                    size_t i1 = ((size_t)(r + 8) * 128 + fcol0 + f) >> 1;
                    bsplit(o0.x, ha, la); bsplit(o0.y, hb, lb);
                    outS[i0] = make_uint2(pk(ha, hb), pk(la, lb));
                    bsplit(o1.x, ha, la); bsplit(o1.y, hb, lb);
                    outS[i1] = make_uint2(pk(ha, hb), pk(la, lb));
                } else {
                    *reinterpret_cast<float2*>(&outF[(size_t)r * 128 + fcol0 + f]) = o0;
                    *reinterpret_cast<float2*>(&outF[(size_t)(r + 8) * 128 + fcol0 + f]) = o1;
                }
            }
        }
        if (G1) {
#pragma unroll
            for (int mask = 4; mask < 32; mask <<= 1) {
#pragma unroll
                for (int n = 0; n < 4; n++) {
#pragma unroll
                    for (int j = 0; j < 2; j++) {
                        cs[n][j] += __shfl_xor_sync(0xffffffffu, cs[n][j], mask);
                        css[n][j] += __shfl_xor_sync(0xffffffffu, css[n][j], mask);
                    }
                }
            }
            if (lane < 4) {
#pragma unroll
                for (int n = 0; n < 4; n++) {
#pragma unroll
                    for (int j = 0; j < 2; j++) {
                        int f = colBase + n * 8 + lane * 2 + j;
                        atomicAdd(&sStats[f], cs[n][j]);
                        atomicAdd(&sStats[128 + f], css[n][j]);
                    }
                }
            }
        }
    }
#undef MMA

    if (G1) {
        __syncthreads();
        if (tid < 256) atomicAdd(&gstats[tid], sStats[tid]);
    }
}

// ---------------- parallel fold BN + SN into split W2eff / b2eff ----------------
__global__ void __launch_bounds__(128) finalize_kernel(
    const float* __restrict__ W2, const float* __restrict__ b2,
    const float* __restrict__ gamma, const float* __restrict__ beta,
    const float* __restrict__ stats, const float* __restrict__ inv_sigma,
    ushort_t* __restrict__ w2hi, ushort_t* __restrict__ w2lo,
    float* __restrict__ b2eff, int N) {
    const int t = blockIdx.x;
    const int f = threadIdx.x;
    float invN = 1.f / (float)N;
    float mean = stats[f] * invN;
    float var = stats[128 + f] * invN - mean * mean;
    float af = gamma[f] * rsqrtf(var + 1e-5f);
    float cf = beta[f] - mean * af;

    float wsn = W2[t * 128 + f] * inv_sigma[1];
    float weff = wsn * af;
    ushort_t hi, lo;
    bsplit(weff, hi, lo);
    w2hi[t * 128 + f] = hi;
    w2lo[t * 128 + f] = lo;

    float v = cf * wsn;
#pragma unroll
    for (int mask = 16; mask > 0; mask >>= 1)
        v += __shfl_xor_sync(0xffffffffu, v, mask);
    __shared__ float sw[4];
    if ((f & 31) == 0) sw[f >> 5] = v;
    __syncthreads();
    if (f == 0) b2eff[t] = b2[t] + sw[0] + sw[1] + sw[2] + sw[3];
}

// ---------------- launch ----------------
extern "C" void kernel_launch(void* const* d_in, const int* in_sizes, int n_in,
                              void* d_out, int out_size) {
    const float* x        = (const float*)d_in[0];
    const void*  ei       = d_in[1];
    const float* W1       = (const float*)d_in[2];
    const float* b1       = (const float*)d_in[3];
    const float* u1       = (const float*)d_in[4];
    const float* gamma    = (const float*)d_in[5];
    const float* beta     = (const float*)d_in[6];
    const float* W2       = (const float*)d_in[7];
    const float* b2       = (const float*)d_in[8];
    const float* u2       = (const float*)d_in[9];

    int N = in_sizes[0] / NFEAT;
    int E = in_sizes[1] / 2;

    float *pAgg, *pStats, *pInv, *pB2eff;
    uint2 *pH1s;
    ushort_t *pW1hi, *pW1lo, *pW2hi, *pW2lo;
    cudaGetSymbolAddress((void**)&pAgg, g_agg);
    cudaGetSymbolAddress((void**)&pH1s, g_h1s);
    cudaGetSymbolAddress((void**)&pStats, g_stats);
    cudaGetSymbolAddress((void**)&pInv, g_inv_sigma);
    cudaGetSymbolAddress((void**)&pB2eff, g_b2eff);
    cudaGetSymbolAddress((void**)&pW1hi, g_w1hi);
    cudaGetSymbolAddress((void**)&pW1lo, g_w1lo);
    cudaGetSymbolAddress((void**)&pW2hi, g_w2hi);
    cudaGetSymbolAddress((void**)&pW2lo, g_w2lo);

    // one-time side stream + fork/join events
    static cudaStream_t s_side = nullptr;
    static cudaEvent_t s_fork = nullptr, s_join = nullptr, s_init = nullptr;
    if (!s_side) {
        cudaStreamCreateWithFlags(&s_side, cudaStreamNonBlocking);
        cudaEventCreateWithFlags(&s_fork, cudaEventDisableTiming);
        cudaEventCreateWithFlags(&s_join, cudaEventDisableTiming);
        cudaEventCreateWithFlags(&s_init, cudaEventDisableTiming);
    }

    // fork: side stream does detect + memset + spectral norms + W1 split
    cudaEventRecord(s_fork, 0);
    cudaStreamWaitEvent(s_side, s_fork, 0);
    detect_kernel<<<1, 64, 0, s_side>>>((const long long*)ei, N);
    cudaMemsetAsync(pAgg, 0, (size_t)N * NFEAT * sizeof(float), s_side);
    cudaEventRecord(s_init, s_side);
    setup_kernel<<<1, 256, 0, s_side>>>(pStats, W1, u1, W2, u2, pInv);
    wsplit1_kernel<<<(NHID * NFEAT + 255) / 256, 256, 0, s_side>>>(W1, pInv, pW1hi, pW1lo);
    cudaEventRecord(s_join, s_side);

    // main stream: wait for detect+memset -> scatter (setup/wsplit overlap it)
    cudaStreamWaitEvent(0, s_init, 0);
    int items = E * 8;
    scatter_kernel<<<(items + 255) / 256, 256>>>(ei, (const float4*)x, (float4*)pAgg, E, N);

    // join before gemm1
    cudaStreamWaitEvent(0, s_join, 0);

    // gemm1: h1(interleaved split) = relu((agg+x) @ W1s^T + b1), fused stats, 2 tiles/block
    {
        constexpr int SAe = NFEAT + 8;
        int smem = (2 * 128 + 2 * 128) * SAe * 2 + (128 + 256) * 4;
        cudaFuncSetAttribute((const void*)gemm_kernel<NFEAT, 128, 1, 2>,
                             cudaFuncAttributeMaxDynamicSharedMemorySize, smem);
        gemm_kernel<NFEAT, 128, 1, 2><<<N / 256, 512, smem>>>(
            pAgg, x, nullptr, pW1hi, pW1lo, b1,
            nullptr, pH1s, pStats);
    }

    // finalize BN+SN fold (parallel, 128x128)
    finalize_kernel<<<128, 128>>>(W2, b2, gamma, beta, pStats, pInv, pW2hi, pW2lo, pB2eff, N);

    // gemm2: out = h1 @ W2eff^T + b2eff  (split-N 128x64, split accumulators, 2 tiles/block)
    {
        constexpr int SAe = NHID + 8;
        int smem = (2 * 128 + 2 * 64) * SAe * 2 + (64 + 256) * 4;
        cudaFuncSetAttribute((const void*)gemm_kernel<NHID, 64, 2, 2>,
                             cudaFuncAttributeMaxDynamicSharedMemorySize, smem);
        gemm_kernel<NHID, 64, 2, 2><<<N / 128, 512, smem>>>(
            nullptr, nullptr, pH1s, pW2hi, pW2lo, pB2eff,
            (float*)d_out, nullptr, nullptr);
    }
}

// round 16
// speedup vs baseline: 1.2174x; 1.0426x over previous
#include <cuda_runtime.h>
#include <cuda_bf16.h>
#include <cstdint>

#define NFEAT 64
#define NHID  128
#define MAXN  65536
#define MAXE  1048576

typedef unsigned long long ull;
typedef unsigned short ushort_t;

// ---------------- device scratch (allocation-free contract) ----------------
__device__ __align__(256) float g_agg[MAXN * NFEAT];         // neighbor sum
__device__ __align__(256) uint2 g_h1s[MAXN * NHID / 2];      // h1 split: {hipair, lopair}
__device__ __align__(256) float g_stats[256];
__device__ __align__(256) float g_inv_sigma[2];
__device__ __align__(256) float g_b2eff[NHID];
__device__ __align__(256) ushort_t g_w1hi[NHID * NFEAT];
__device__ __align__(256) ushort_t g_w1lo[NHID * NFEAT];
__device__ __align__(256) ushort_t g_w2hi[NHID * NHID];
__device__ __align__(256) ushort_t g_w2lo[NHID * NHID];
__device__ __align__(256) int g_deg[MAXN];
__device__ __align__(256) int g_rowptr[MAXN + 1];
__device__ __align__(256) int g_cursor[MAXN];
__device__ __align__(256) int g_adj[MAXE];
__device__ __align__(256) int g_partials[256];
__device__ int g_idx_mode;

// ---------------- helpers ----------------
__device__ __forceinline__ void bsplit(float v, ushort_t& hi, ushort_t& lo) {
    __nv_bfloat16 h = __float2bfloat16(v);
    float r = v - __bfloat162float(h);
    __nv_bfloat16 l = __float2bfloat16(r);
    hi = __bfloat16_as_ushort(h);
    lo = __bfloat16_as_ushort(l);
}
__device__ __forceinline__ unsigned pk(ushort_t a, ushort_t b) {
    return (unsigned)a | ((unsigned)b << 16);
}
__device__ __forceinline__ void ldsm4(unsigned& r0, unsigned& r1, unsigned& r2, unsigned& r3,
                                      unsigned addr) {
    asm volatile("ldmatrix.sync.aligned.m8n8.x4.shared.b16 {%0,%1,%2,%3}, [%4];"
                 : "=r"(r0), "=r"(r1), "=r"(r2), "=r"(r3) : "r"(addr));
}
__device__ __forceinline__ unsigned smem_u32(const void* p) {
    return (unsigned)__cvta_generic_to_shared(p);
}
__device__ __forceinline__ void cpasync16(unsigned smaddr, const void* g) {
    asm volatile("cp.async.cg.shared.global [%0], [%1], 16;" :: "r"(smaddr), "l"(g));
}
#define CP_COMMIT() asm volatile("cp.async.commit_group;" ::: "memory")
#define CP_WAIT0()  asm volatile("cp.async.wait_group 0;" ::: "memory")

__device__ __forceinline__ void load_edge(const void* eiv, int E, int e,
                                          long long& s, long long& d) {
    if (g_idx_mode == 0) {
        const long long* ei = (const long long*)eiv;
        s = ei[e]; d = ei[E + e];
    } else {
        const int* ei = (const int*)eiv;
        s = ei[e]; d = ei[E + e];
    }
}

// ---------------- edge dtype probe ----------------
__global__ void detect_kernel(const long long* __restrict__ ei64, int N) {
    int t = threadIdx.x;  // 64 threads
    long long v = ei64[t];
    unsigned bad = __ballot_sync(0xffffffffu, (v < 0 || v >= (long long)N));
    __shared__ unsigned sb[2];
    if ((t & 31) == 0) sb[t >> 5] = bad;
    __syncthreads();
    if (t == 0) g_idx_mode = (sb[0] | sb[1]) ? 1 : 0;
}

// ---------------- CSR build ----------------
__global__ void hist_kernel(const void* __restrict__ eiv, int* __restrict__ deg,
                            int E, int N) {
    int e = blockIdx.x * blockDim.x + threadIdx.x;
    if (e >= E) return;
    long long s, d;
    load_edge(eiv, E, e, s, d);
    if ((ull)d >= (ull)N || (ull)s >= (ull)N) return;
    atomicAdd(&deg[(int)d], 1);
}

// block b sums deg[b*256 .. +255] -> partials[b]
__global__ void scan1_kernel(const int* __restrict__ deg, int* __restrict__ partials) {
    __shared__ int sd[256];
    int t = threadIdx.x;
    sd[t] = deg[blockIdx.x * 256 + t];
    __syncthreads();
    for (int s = 128; s > 0; s >>= 1) {
        if (t < s) sd[t] += sd[t + s];
        __syncthreads();
    }
    if (t == 0) partials[blockIdx.x] = sd[0];
}

// exclusive scan of 256 partials; rowptr[N] = total
__global__ void scan2_kernel(int* __restrict__ partials, int* __restrict__ rowptr, int N) {
    __shared__ int sd[256];
    int t = threadIdx.x;
    int orig = partials[t];
    sd[t] = orig;
    __syncthreads();
    for (int off = 1; off < 256; off <<= 1) {
        int v = (t >= off) ? sd[t - off] : 0;
        __syncthreads();
        sd[t] += v;
        __syncthreads();
    }
    partials[t] = sd[t] - orig;            // exclusive
    if (t == 255) rowptr[N] = sd[255];     // total
}

// per-block exclusive scan + partial offset -> rowptr, cursor
__global__ void scan3_kernel(const int* __restrict__ deg, const int* __restrict__ partials,
                             int* __restrict__ rowptr, int* __restrict__ cursor) {
    __shared__ int sd[256];
    int t = threadIdx.x;
    int i = blockIdx.x * 256 + t;
    int orig = deg[i];
    sd[t] = orig;
    __syncthreads();
    for (int off = 1; off < 256; off <<= 1) {
        int v = (t >= off) ? sd[t - off] : 0;
        __syncthreads();
        sd[t] += v;
        __syncthreads();
    }
    int val = partials[blockIdx.x] + sd[t] - orig;
    rowptr[i] = val;
    cursor[i] = val;
}

__global__ void fill_kernel(const void* __restrict__ eiv, int* __restrict__ cursor,
                            int* __restrict__ adj, int E, int N) {
    int e = blockIdx.x * blockDim.x + threadIdx.x;
    if (e >= E) return;
    long long s, d;
    load_edge(eiv, E, e, s, d);
    if ((ull)d >= (ull)N || (ull)s >= (ull)N) return;
    int pos = atomicAdd(&cursor[(int)d], 1);
    adj[pos] = (int)s;
}

// ---------------- pull-gather: agg[d] = sum_{s in adj[d]} x[s] ----------------
// 16 threads per node, one float4 column each. No RMW: single store per element.
__global__ void gather_kernel(const int* __restrict__ rowptr, const int* __restrict__ adj,
                              const float4* __restrict__ x4, float4* __restrict__ agg4,
                              int N) {
    int gi = blockIdx.x * blockDim.x + threadIdx.x;
    int d = gi >> 4;
    int c = gi & 15;
    if (d >= N) return;
    int j = rowptr[d];
    const int end = rowptr[d + 1];
    float4 acc = make_float4(0.f, 0.f, 0.f, 0.f);
    for (; j + 1 < end; j += 2) {
        int s0 = adj[j], s1 = adj[j + 1];
        float4 v0 = __ldcg(x4 + (size_t)s0 * 16 + c);
        float4 v1 = __ldcg(x4 + (size_t)s1 * 16 + c);
        acc.x += v0.x + v1.x; acc.y += v0.y + v1.y;
        acc.z += v0.z + v1.z; acc.w += v0.w + v1.w;
    }
    if (j < end) {
        int s0 = adj[j];
        float4 v0 = __ldcg(x4 + (size_t)s0 * 16 + c);
        acc.x += v0.x; acc.y += v0.y; acc.z += v0.z; acc.w += v0.w;
    }
    agg4[(size_t)d * 16 + c] = acc;
}

// ---------------- setup: stats zero + spectral norms (side stream) ----------------
__device__ float block_reduce_sum256(float v, float* sred) {
    int t = threadIdx.x;
    sred[t] = v;
    __syncthreads();
    for (int s = 128; s > 0; s >>= 1) {
        if (t < s) sred[t] += sred[t + s];
        __syncthreads();
    }
    float r = sred[0];
    __syncthreads();
    return r;
}

__device__ float inv_sigma_calc(const float* __restrict__ W, const float* __restrict__ u,
                                int n, int m, float* sv, float* swv, float* sred) {
    int t = threadIdx.x;
    float vt = 0.f;
    if (t < m) {
#pragma unroll 4
        for (int i = 0; i < n; i++) vt += W[i * m + t] * u[i];
    }
    float s = block_reduce_sum256((t < m) ? vt * vt : 0.f, sred);
    if (t < m) sv[t] = vt / (sqrtf(s) + 1e-12f);
    __syncthreads();
    int warp = t >> 5, lane = t & 31;
    for (int row = warp; row < n; row += 8) {
        float p = 0.f;
        for (int k = lane; k < m; k += 32) p += W[row * m + k] * sv[k];
#pragma unroll
        for (int mask = 16; mask > 0; mask >>= 1)
            p += __shfl_xor_sync(0xffffffffu, p, mask);
        if (lane == 0) swv[row] = p;
    }
    __syncthreads();
    float z = (t < n) ? swv[t] * swv[t] : 0.f;
    float s2 = block_reduce_sum256(z, sred);
    float sig = s2 / (sqrtf(s2) + 1e-12f);
    return 1.f / sig;
}

__global__ void setup_kernel(float* __restrict__ stats,
                             const float* __restrict__ W1, const float* __restrict__ u1,
                             const float* __restrict__ W2, const float* __restrict__ u2,
                             float* __restrict__ inv_sigma) {
    __shared__ float sv[128];
    __shared__ float swv[128];
    __shared__ float sred[256];
    int t = threadIdx.x;
    stats[t] = 0.f;

    float is1 = inv_sigma_calc(W1, u1, NHID, NFEAT, sv, swv, sred);
    float is2 = inv_sigma_calc(W2, u2, NHID, NHID, sv, swv, sred);
    if (t == 0) { inv_sigma[0] = is1; inv_sigma[1] = is2; }
}

// ---------------- parallel W1 split ----------------
__global__ void wsplit1_kernel(const float* __restrict__ W1,
                               const float* __restrict__ inv_sigma,
                               ushort_t* __restrict__ w1hi, ushort_t* __restrict__ w1lo) {
    int i = blockIdx.x * blockDim.x + threadIdx.x;
    if (i >= NHID * NFEAT) return;
    float w = W1[i] * inv_sigma[0];
    ushort_t hi, lo;
    bsplit(w, hi, lo);
    w1hi[i] = hi;
    w1lo[i] = lo;
}

// ---------------- tensor-core GEMM, hi/lo segments, ldmatrix + cp.async ----------------
// MODE 1 (gemm1): A = agg+x (fp32, split on the fly), relu, fused stats, h1 interleaved out.
// MODE 2 (gemm2): A = interleaved pre-split h1 (deinterleave fill), fp32 out.
template <int K, int NC, int MODE>
__global__ void __launch_bounds__(512, 2) gemm_kernel(
    const float* __restrict__ inF, const float* __restrict__ xadd,
    const uint2* __restrict__ inS,
    const ushort_t* __restrict__ whi, const ushort_t* __restrict__ wlo,
    const float* __restrict__ bias,
    float* __restrict__ outF, uint2* __restrict__ outS,
    float* __restrict__ gstats) {
    constexpr bool G1 = (MODE == 1);
    constexpr int SAe = K + 8;
    constexpr int K4 = K / 4;
    constexpr int R8 = K / 8;
    constexpr int CW = NC / 32;
    constexpr int MT = 128 / ((16 / CW) * 16);
    constexpr int CB = 128 / NC;
    constexpr bool SPLITX = (MT == 1);

    extern __shared__ ushort_t smu[];
    ushort_t* sAhi = smu;                        // 128*SAe
    ushort_t* sAlo = sAhi + 128 * SAe;
    ushort_t* sBhi = sAlo + 128 * SAe;           // NC*SAe
    ushort_t* sBlo = sBhi + NC * SAe;
    float* sBias   = reinterpret_cast<float*>(sBlo + NC * SAe);
    float* sStats  = sBias + NC;

    const int tid = threadIdx.x;
    const int cb = blockIdx.x % CB;
    const int row0 = (blockIdx.x / CB) * 128;
    const int fcol0 = cb * NC;

    // ---- B fill via cp.async ----
    {
        const uint4* ghi = reinterpret_cast<const uint4*>(whi + (size_t)fcol0 * K);
        const uint4* glo = reinterpret_cast<const uint4*>(wlo + (size_t)fcol0 * K);
#pragma unroll
        for (int q = tid; q < NC * R8; q += 512) {
            int f = q / R8, c = q - f * R8;
            cpasync16(smem_u32(&sBhi[f * SAe + c * 8]), ghi + q);
            cpasync16(smem_u32(&sBlo[f * SAe + c * 8]), glo + q);
        }
        CP_COMMIT();
    }
    if (tid < NC) sBias[tid] = bias[fcol0 + tid];
    if (G1 && tid < 256) sStats[tid] = 0.f;

    // ---- A fill ----
    if (G1) {
        const float4* in4 = reinterpret_cast<const float4*>(inF);
        const float4* x4 = reinterpret_cast<const float4*>(xadd);
#pragma unroll
        for (int q = tid; q < 128 * K4; q += 512) {
            int r = q / K4, c = q - r * K4;
            size_t gi = (size_t)(row0 + r) * K4 + c;
            float4 v = __ldcg(in4 + gi);
            float4 w = __ldcg(x4 + gi);
            v.x += w.x; v.y += w.y; v.z += w.z; v.w += w.w;
            ushort_t h0, l0, h1, l1, h2, l2, h3, l3;
            bsplit(v.x, h0, l0); bsplit(v.y, h1, l1);
            bsplit(v.z, h2, l2); bsplit(v.w, h3, l3);
            uint2 hw, lw;
            hw.x = pk(h0, h1); hw.y = pk(h2, h3);
            lw.x = pk(l0, l1); lw.y = pk(l2, l3);
            *reinterpret_cast<uint2*>(&sAhi[r * SAe + c * 4]) = hw;
            *reinterpret_cast<uint2*>(&sAlo[r * SAe + c * 4]) = lw;
        }
    } else {
        const uint4* gs = reinterpret_cast<const uint4*>(inS);
        constexpr int RW = K / 4;
#pragma unroll
        for (int q = tid; q < 128 * RW; q += 512) {
            int r = q / RW, c = q - r * RW;
            uint4 v = __ldcg(gs + (size_t)(row0 + r) * RW + c);
            *reinterpret_cast<uint2*>(&sAhi[r * SAe + c * 4]) = make_uint2(v.x, v.z);
            *reinterpret_cast<uint2*>(&sAlo[r * SAe + c * 4]) = make_uint2(v.y, v.w);
        }
    }
    CP_WAIT0();
    __syncthreads();

    const int wid = tid >> 5;
    const int lane = tid & 31;
    const int g = lane >> 2;
    const int tg = lane & 3;
    const int rowBase = (wid / CW) * (MT * 16);
    const int colBase = (wid % CW) * 32;

    float acc[MT][4][4];
    float accX[SPLITX ? MT : 1][4][4];
#pragma unroll
    for (int m = 0; m < MT; m++)
#pragma unroll
        for (int n = 0; n < 4; n++)
#pragma unroll
            for (int i = 0; i < 4; i++) {
                acc[m][n][i] = 0.f;
                if (SPLITX) accX[m][n][i] = 0.f;
            }

    const unsigned aRow = rowBase + (lane & 15);
    const unsigned aKH = (lane >> 4) * 8;
    const unsigned aHiBase = smem_u32(sAhi) + (aRow * SAe + aKH) * 2;
    const unsigned aLoBase = smem_u32(sAlo) + (aRow * SAe + aKH) * 2;
    const unsigned bRow = colBase + (lane & 7) + ((lane >> 4) << 3);
    const unsigned bKH = ((lane >> 3) & 1) * 8;
    const unsigned bHiBase = smem_u32(sBhi) + (bRow * SAe + bKH) * 2;
    const unsigned bLoBase = smem_u32(sBlo) + (bRow * SAe + bKH) * 2;
    constexpr unsigned MSTEP = 16 * SAe * 2;

#define MMA(ACC, A0, A1, A2, A3, B0, B1)                                       \
    asm volatile(                                                              \
        "mma.sync.aligned.m16n8k16.row.col.f32.bf16.bf16.f32 "                 \
        "{%0,%1,%2,%3}, {%4,%5,%6,%7}, {%8,%9}, {%0,%1,%2,%3};"                \
        : "+f"((ACC)[0]), "+f"((ACC)[1]), "+f"((ACC)[2]), "+f"((ACC)[3])       \
        : "r"(A0), "r"(A1), "r"(A2), "r"(A3), "r"(B0), "r"(B1))

#pragma unroll
    for (int kk = 0; kk < K / 16; kk++) {
        const unsigned ko2 = kk * 32;
        unsigned ahi[MT][4], bhi[2][4], blo[2][4], alo[MT][4];
#pragma unroll
        for (int m = 0; m < MT; m++)
            ldsm4(ahi[m][0], ahi[m][1], ahi[m][2], ahi[m][3], aHiBase + ko2 + m * MSTEP);
#pragma unroll
        for (int p = 0; p < 2; p++)
            ldsm4(bhi[p][0], bhi[p][1], bhi[p][2], bhi[p][3], bHiBase + ko2 + p * MSTEP);
#pragma unroll
        for (int m = 0; m < MT; m++)
#pragma unroll
            for (int n = 0; n < 4; n++)
                MMA(acc[m][n], ahi[m][0], ahi[m][1], ahi[m][2], ahi[m][3],
                    bhi[n >> 1][(n & 1) * 2], bhi[n >> 1][(n & 1) * 2 + 1]);
#pragma unroll
        for (int p = 0; p < 2; p++)
            ldsm4(blo[p][0], blo[p][1], blo[p][2], blo[p][3], bLoBase + ko2 + p * MSTEP);
#pragma unroll
        for (int m = 0; m < MT; m++)
#pragma unroll
            for (int n = 0; n < 4; n++) {
                if (SPLITX)
                    MMA(accX[m][n], ahi[m][0], ahi[m][1], ahi[m][2], ahi[m][3],
                        blo[n >> 1][(n & 1) * 2], blo[n >> 1][(n & 1) * 2 + 1]);
                else
                    MMA(acc[m][n], ahi[m][0], ahi[m][1], ahi[m][2], ahi[m][3],
                        blo[n >> 1][(n & 1) * 2], blo[n >> 1][(n & 1) * 2 + 1]);
            }
#pragma unroll
        for (int m = 0; m < MT; m++)
            ldsm4(alo[m][0], alo[m][1], alo[m][2], alo[m][3], aLoBase + ko2 + m * MSTEP);
#pragma unroll
        for (int m = 0; m < MT; m++)
#pragma unroll
            for (int n = 0; n < 4; n++) {
                if (SPLITX)
                    MMA(accX[m][n], alo[m][0], alo[m][1], alo[m][2], alo[m][3],
                        bhi[n >> 1][(n & 1) * 2], bhi[n >> 1][(n & 1) * 2 + 1]);
                else
                    MMA(acc[m][n], alo[m][0], alo[m][1], alo[m][2], alo[m][3],
                        bhi[n >> 1][(n & 1) * 2], bhi[n >> 1][(n & 1) * 2 + 1]);
            }
    }
#undef MMA

    if (SPLITX) {
#pragma unroll
        for (int m = 0; m < MT; m++)
#pragma unroll
            for (int n = 0; n < 4; n++)
#pragma unroll
                for (int i = 0; i < 4; i++) acc[m][n][i] += accX[m][n][i];
    }

    // ---- epilogue ----
    float cs[4][2], css[4][2];
    if (G1) {
#pragma unroll
        for (int n = 0; n < 4; n++) { cs[n][0] = cs[n][1] = css[n][0] = css[n][1] = 0.f; }
    }
#pragma unroll
    for (int m = 0; m < MT; m++) {
        int r = row0 + rowBase + m * 16 + g;
#pragma unroll
        for (int n = 0; n < 4; n++) {
            int f = colBase + n * 8 + tg * 2;
            float bx = sBias[f], by = sBias[f + 1];
            float2 o0 = make_float2(acc[m][n][0] + bx, acc[m][n][1] + by);
            float2 o1 = make_float2(acc[m][n][2] + bx, acc[m][n][3] + by);
            if (G1) {
                o0.x = fmaxf(o0.x, 0.f); o0.y = fmaxf(o0.y, 0.f);
                o1.x = fmaxf(o1.x, 0.f); o1.y = fmaxf(o1.y, 0.f);
                cs[n][0] += o0.x + o1.x;  cs[n][1] += o0.y + o1.y;
                css[n][0] += o0.x * o0.x + o1.x * o1.x;
                css[n][1] += o0.y * o0.y + o1.y * o1.y;
                ushort_t ha, la, hb, lb;
                size_t i0 = ((size_t)r * 128 + fcol0 + f) >> 1;
                size_t i1 = ((size_t)(r + 8) * 128 + fcol0 + f) >> 1;
                bsplit(o0.x, ha, la); bsplit(o0.y, hb, lb);
                outS[i0] = make_uint2(pk(ha, hb), pk(la, lb));
                bsplit(o1.x, ha, la); bsplit(o1.y, hb, lb);
                outS[i1] = make_uint2(pk(ha, hb), pk(la, lb));
            } else {
                *reinterpret_cast<float2*>(&outF[(size_t)r * 128 + fcol0 + f]) = o0;
                *reinterpret_cast<float2*>(&outF[(size_t)(r + 8) * 128 + fcol0 + f]) = o1;
            }
        }
    }
    if (G1) {
#pragma unroll
        for (int mask = 4; mask < 32; mask <<= 1) {
#pragma unroll
            for (int n = 0; n < 4; n++) {
#pragma unroll
                for (int j = 0; j < 2; j++) {
                    cs[n][j] += __shfl_xor_sync(0xffffffffu, cs[n][j], mask);
                    css[n][j] += __shfl_xor_sync(0xffffffffu, css[n][j], mask);
                }
            }
        }
        if (lane < 4) {
#pragma unroll
            for (int n = 0; n < 4; n++) {
#pragma unroll
                for (int j = 0; j < 2; j++) {
                    int f = colBase + n * 8 + lane * 2 + j;
                    atomicAdd(&sStats[f], cs[n][j]);
                    atomicAdd(&sStats[128 + f], css[n][j]);
                }
            }
        }
        __syncthreads();
        if (tid < 256) atomicAdd(&gstats[tid], sStats[tid]);
    }
}

// ---------------- parallel fold BN + SN into split W2eff / b2eff ----------------
__global__ void __launch_bounds__(128) finalize_kernel(
    const float* __restrict__ W2, const float* __restrict__ b2,
    const float* __restrict__ gamma, const float* __restrict__ beta,
    const float* __restrict__ stats, const float* __restrict__ inv_sigma,
    ushort_t* __restrict__ w2hi, ushort_t* __restrict__ w2lo,
    float* __restrict__ b2eff, int N) {
    const int t = blockIdx.x;
    const int f = threadIdx.x;
    float invN = 1.f / (float)N;
    float mean = stats[f] * invN;
    float var = stats[128 + f] * invN - mean * mean;
    float af = gamma[f] * rsqrtf(var + 1e-5f);
    float cf = beta[f] - mean * af;

    float wsn = W2[t * 128 + f] * inv_sigma[1];
    float weff = wsn * af;
    ushort_t hi, lo;
    bsplit(weff, hi, lo);
    w2hi[t * 128 + f] = hi;
    w2lo[t * 128 + f] = lo;

    float v = cf * wsn;
#pragma unroll
    for (int mask = 16; mask > 0; mask >>= 1)
        v += __shfl_xor_sync(0xffffffffu, v, mask);
    __shared__ float sw[4];
    if ((f & 31) == 0) sw[f >> 5] = v;
    __syncthreads();
    if (f == 0) b2eff[t] = b2[t] + sw[0] + sw[1] + sw[2] + sw[3];
}

// ---------------- launch ----------------
extern "C" void kernel_launch(void* const* d_in, const int* in_sizes, int n_in,
                              void* d_out, int out_size) {
    const float* x        = (const float*)d_in[0];
    const void*  ei       = d_in[1];
    const float* W1       = (const float*)d_in[2];
    const float* b1       = (const float*)d_in[3];
    const float* u1       = (const float*)d_in[4];
    const float* gamma    = (const float*)d_in[5];
    const float* beta     = (const float*)d_in[6];
    const float* W2       = (const float*)d_in[7];
    const float* b2       = (const float*)d_in[8];
    const float* u2       = (const float*)d_in[9];

    int N = in_sizes[0] / NFEAT;
    int E = in_sizes[1] / 2;

    float *pAgg, *pStats, *pInv, *pB2eff;
    uint2 *pH1s;
    ushort_t *pW1hi, *pW1lo, *pW2hi, *pW2lo;
    int *pDeg, *pRowptr, *pCursor, *pAdj, *pPartials;
    cudaGetSymbolAddress((void**)&pAgg, g_agg);
    cudaGetSymbolAddress((void**)&pH1s, g_h1s);
    cudaGetSymbolAddress((void**)&pStats, g_stats);
    cudaGetSymbolAddress((void**)&pInv, g_inv_sigma);
    cudaGetSymbolAddress((void**)&pB2eff, g_b2eff);
    cudaGetSymbolAddress((void**)&pW1hi, g_w1hi);
    cudaGetSymbolAddress((void**)&pW1lo, g_w1lo);
    cudaGetSymbolAddress((void**)&pW2hi, g_w2hi);
    cudaGetSymbolAddress((void**)&pW2lo, g_w2lo);
    cudaGetSymbolAddress((void**)&pDeg, g_deg);
    cudaGetSymbolAddress((void**)&pRowptr, g_rowptr);
    cudaGetSymbolAddress((void**)&pCursor, g_cursor);
    cudaGetSymbolAddress((void**)&pAdj, g_adj);
    cudaGetSymbolAddress((void**)&pPartials, g_partials);

    // one-time side stream + fork/join events
    static cudaStream_t s_side = nullptr;
    static cudaEvent_t s_fork = nullptr, s_join = nullptr;
    if (!s_side) {
        cudaStreamCreateWithFlags(&s_side, cudaStreamNonBlocking);
        cudaEventCreateWithFlags(&s_fork, cudaEventDisableTiming);
        cudaEventCreateWithFlags(&s_join, cudaEventDisableTiming);
    }

    // fork: side stream does spectral norms + W1 split
    cudaEventRecord(s_fork, 0);
    cudaStreamWaitEvent(s_side, s_fork, 0);
    setup_kernel<<<1, 256, 0, s_side>>>(pStats, W1, u1, W2, u2, pInv);
    wsplit1_kernel<<<(NHID * NFEAT + 255) / 256, 256, 0, s_side>>>(W1, pInv, pW1hi, pW1lo);
    cudaEventRecord(s_join, s_side);

    // main stream: CSR build + pull gather
    detect_kernel<<<1, 64>>>((const long long*)ei, N);
    cudaMemsetAsync(pDeg, 0, (size_t)N * sizeof(int));
    hist_kernel<<<(E + 255) / 256, 256>>>(ei, pDeg, E, N);
    scan1_kernel<<<N / 256, 256>>>(pDeg, pPartials);
    scan2_kernel<<<1, 256>>>(pPartials, pRowptr, N);
    scan3_kernel<<<N / 256, 256>>>(pDeg, pPartials, pRowptr, pCursor);
    fill_kernel<<<(E + 255) / 256, 256>>>(ei, pCursor, pAdj, E, N);
    gather_kernel<<<(N * 16) / 256, 256>>>(pRowptr, pAdj, (const float4*)x,
                                           (float4*)pAgg, N);

    // join before gemm1
    cudaStreamWaitEvent(0, s_join, 0);

    // gemm1: h1(interleaved split) = relu((agg+x) @ W1s^T + b1), fused stats
    {
        constexpr int SAe = NFEAT + 8;
        int smem = (2 * 128 + 2 * 128) * SAe * 2 + (128 + 256) * 4;
        cudaFuncSetAttribute((const void*)gemm_kernel<NFEAT, 128, 1>,
                             cudaFuncAttributeMaxDynamicSharedMemorySize, smem);
        gemm_kernel<NFEAT, 128, 1><<<N / 128, 512, smem>>>(
            pAgg, x, nullptr, pW1hi, pW1lo, b1,
            nullptr, pH1s, pStats);
    }

    // finalize BN+SN fold
    finalize_kernel<<<128, 128>>>(W2, b2, gamma, beta, pStats, pInv, pW2hi, pW2lo, pB2eff, N);

    // gemm2: out = h1 @ W2eff^T + b2eff  (split-N 128x64, split accumulators)
    {
        constexpr int SAe = NHID + 8;
        int smem = (2 * 128 + 2 * 64) * SAe * 2 + (64 + 256) * 4;
        cudaFuncSetAttribute((const void*)gemm_kernel<NHID, 64, 2>,
                             cudaFuncAttributeMaxDynamicSharedMemorySize, smem);
        gemm_kernel<NHID, 64, 2><<<(N / 128) * 2, 512, smem>>>(
            nullptr, nullptr, pH1s, pW2hi, pW2lo, pB2eff,
            (float*)d_out, nullptr, nullptr);
    }
}